// round 11
// baseline (speedup 1.0000x reference)
#include <cuda_runtime.h>
#include <cuda_bf16.h>
#include <math.h>

#define BATCH 16384
#define FF    39
#define DD    16
#define DHD   32
#define VOCAB 10000
#define WARPS 14
#define NCTA  ((BATCH + WARPS - 1) / WARPS)   // 1171 -> 7.91 waves on 148 SMs

// per-warp shared layout (float indices):
//  e:       [0,1248)          e / R / new-e (pitch 32)
//  kT:      [1248,2608)       40 rows x pitch 34; row 39 = zeros (persistent)
//  vstage:  [2608,3920)       32 x pitch 41, PASS-1 ONLY (then dead)
//  qB:      [2608,3856)       39 x pitch 32, pass2+ (aliases dead vstage)
//  sr0:     [3856,3896)       sr0[39] re-zeroed per layer (vstage clobbers it)
//  sr1:     [3896,3936)       sr1[39] init once (never clobbered)
//  mA/mB:   [1248,1376)/[1376,1440)  MLP hidden, over dead kT
#define KT_OFF   1248
#define KT_PITCH 34
#define VS_OFF   2608
#define VS_PITCH 41
#define QB_OFF   2608
#define QB_PITCH 32
#define S_OFF    3856
#define MA_OFF   1248
#define MB_OFF   1376
#define PW       3936
#define WBUF     2048          // CTA w1 chunk: 1024 ull = 16 k-rows x 128 (8KB)

#define LOG2E 1.4426950408889634f

typedef unsigned long long ull;

__device__ __forceinline__ ull ffma2(ull a, ull b, ull c) {
  ull d; asm("fma.rn.f32x2 %0, %1, %2, %3;" : "=l"(d) : "l"(a), "l"(b), "l"(c));
  return d;
}
__device__ __forceinline__ ull fadd2(ull a, ull b) {
  ull d; asm("add.rn.f32x2 %0, %1, %2;" : "=l"(d) : "l"(a), "l"(b));
  return d;
}
__device__ __forceinline__ ull pack2(float lo, float hi) {
  ull v; unsigned int l = __float_as_uint(lo), h = __float_as_uint(hi);
  asm("mov.b64 %0, {%1, %2};" : "=l"(v) : "r"(l), "r"(h));
  return v;
}
__device__ __forceinline__ float hsum2(ull v) {
  unsigned int l, h;
  asm("mov.b64 {%0, %1}, %2;" : "=r"(l), "=r"(h) : "l"(v));
  return __uint_as_float(l) + __uint_as_float(h);
}
__device__ __forceinline__ float frcp(float x) {
  float r; asm("rcp.approx.f32 %0, %1;" : "=f"(r) : "f"(x));
  return r;
}
__device__ __forceinline__ float fex2(float x) {
  float r; asm("ex2.approx.f32 %0, %1;" : "=f"(r) : "f"(x));
  return r;
}
__device__ __forceinline__ void cfence() { asm volatile("" ::: "memory"); }

struct Params {
  const int* x; const float* emb;
  const float* wq0; const float* wk0; const float* wv0; const float* wr0;
  const float* wq1; const float* wk1; const float* wv1; const float* wr1;
  const float* wq2; const float* wk2; const float* wv2; const float* wr2;
  const float* w1; const float* b1; const float* w2; const float* b2;
  const float* w3; const float* b3; const float* w4; const float* b4;
  float* out;
};

template<int DIN>
__device__ __forceinline__ void attn_layer(
    float* wp,
    const float* __restrict__ wq, const float* __restrict__ wk,
    const float* __restrict__ wv, const float* __restrict__ wr, int lane)
{
  float* eB  = wp;
  float* kT  = wp + KT_OFF;
  float* vS  = wp + VS_OFF;
  float* qB  = wp + QB_OFF;
  float* sr0 = wp + S_OFF;
  float* sr1 = wp + S_OFF + 40;
  constexpr int NP = DIN / 2;

  // ---- Pass 1: K -> kT (transposed), V -> vstage. Live: wk/wv packs only. ----
  {
    ull wkp[NP], wvp[NP];
    #pragma unroll
    for (int dp = 0; dp < NP; dp++) {
      wkp[dp] = pack2(wk[(2*dp)*DHD + lane], wk[(2*dp+1)*DHD + lane]);
      wvp[dp] = pack2(wv[(2*dp)*DHD + lane], wv[(2*dp+1)*DHD + lane]);
    }
    #pragma unroll 2
    for (int g = 0; g < FF; g++) {
      const ulonglong2* er = (const ulonglong2*)(eB + g*DHD);
      ull ka = 0ull, kb = 0ull, va = 0ull, vb = 0ull;
      #pragma unroll
      for (int q8 = 0; q8 < NP/2; q8++) {
        ulonglong2 ev = er[q8];
        ka = ffma2(ev.x, wkp[2*q8],   ka);  va = ffma2(ev.x, wvp[2*q8],   va);
        kb = ffma2(ev.y, wkp[2*q8+1], kb);  vb = ffma2(ev.y, wvp[2*q8+1], vb);
      }
      kT[g*KT_PITCH + lane] = hsum2(fadd2(ka, kb));
      vS[lane*VS_PITCH + g] = hsum2(fadd2(va, vb));   // pitch 41: conflict-free
    }
  }
  cfence();

  // ---- vp register load NOW (before qB overwrites vstage). Live: vp(40). ----
  ull vp[20];
  {
    const float* vr = vS + lane*VS_PITCH;
    #pragma unroll
    for (int gp = 0; gp < 19; gp++)
      vp[gp] = pack2(vr[2*gp], vr[2*gp+1]);
    vp[19] = pack2(vr[38], 0.f);
  }
  if (lane == 0) sr0[39] = 0.f;   // vstage clobbered it; sr1[39] is never touched
  cfence();

  // ---- Pass 2: Q (pre-scaled log2e) -> qB (over dead vstage), R -> eB.
  //      Live: wq/wr packs (64) + vp (40). klo/khi NOT yet loaded. ----
  {
    ull wqp[NP], wrp[NP];
    #pragma unroll
    for (int dp = 0; dp < NP; dp++) {
      wqp[dp] = pack2(wq[(2*dp)*DHD + lane] * LOG2E, wq[(2*dp+1)*DHD + lane] * LOG2E);
      wrp[dp] = pack2(wr[(2*dp)*DHD + lane], wr[(2*dp+1)*DHD + lane]);
    }
    #pragma unroll 2
    for (int g = 0; g < FF; g++) {
      const ulonglong2* er = (const ulonglong2*)(eB + g*DHD);
      ull qa = 0ull, qb = 0ull, ra = 0ull, rb = 0ull;
      #pragma unroll
      for (int q8 = 0; q8 < NP/2; q8++) {
        ulonglong2 ev = er[q8];
        qa = ffma2(ev.x, wqp[2*q8],   qa);  ra = ffma2(ev.x, wrp[2*q8],   ra);
        qb = ffma2(ev.y, wqp[2*q8+1], qb);  rb = ffma2(ev.y, wrp[2*q8+1], rb);
      }
      qB[g*QB_PITCH + lane] = hsum2(fadd2(qa, qb));
      eB[g*DHD + lane]      = hsum2(fadd2(ra, rb));   // R over dead e
    }
  }
  cfence();

  // ---- klo/khi register load AFTER pass 2 (weights dead). ----
  ull klo[16], khi[16];
  {
    const int hrow = (lane < 7) ? (lane + 32) : 39;   // row 39 is zeros
    #pragma unroll
    for (int dp = 0; dp < 16; dp++) {
      klo[dp] = *(const ull*)&kT[lane*KT_PITCH + 2*dp];
      khi[dp] = *(const ull*)&kT[hrow*KT_PITCH + 2*dp];
    }
  }
  cfence();

  const bool has2 = (lane < 7);

  // ---- Phase B: scores, deferred-norm softmax (butterfly sum), AV ----
  #pragma unroll 2
  for (int f = 0; f < FF; f++) {
    float* srf = (f & 1) ? sr1 : sr0;
    const ulonglong2* q2 = (const ulonglong2*)(qB + f*QB_PITCH);
    ull s1a = 0ull, s1b = 0ull, s2a = 0ull, s2b = 0ull;
    #pragma unroll
    for (int q8 = 0; q8 < 8; q8++) {
      ulonglong2 qv = q2[q8];
      s1a = ffma2(qv.x, klo[2*q8],   s1a);  s2a = ffma2(qv.x, khi[2*q8],   s2a);
      s1b = ffma2(qv.y, klo[2*q8+1], s1b);  s2b = ffma2(qv.y, khi[2*q8+1], s2b);
    }
    // scores tiny (inputs ~N(0,0.05)): softmax w/o max-sub; Q pre-scaled, p = 2^s
    float p1 = fex2(hsum2(fadd2(s1a, s1b)));
    float p2 = fex2(hsum2(fadd2(s2a, s2b)));
    srf[lane] = p1;
    if (has2) srf[lane + 32] = p2;

    // normalizer via butterfly (independent of the AV chain below)
    float sum = p1 + (has2 ? p2 : 0.f);
    #pragma unroll
    for (int o = 16; o; o >>= 1) sum += __shfl_xor_sync(0xffffffffu, sum, o);
    cfence();

    const ulonglong2* s4 = (const ulonglong2*)srf;
    ull aa = 0ull, ab = 0ull;
    #pragma unroll
    for (int g4 = 0; g4 < 10; g4++) {
      ulonglong2 sv = s4[g4];
      aa = ffma2(sv.x, vp[2*g4],   aa);
      ab = ffma2(sv.y, vp[2*g4+1], ab);
    }
    float inv = frcp(sum);
    float acc = hsum2(fadd2(aa, ab));
    float r   = eB[f*DHD + lane];
    eB[f*DHD + lane] = fmaxf(fmaf(acc, inv, r), 0.f);
    cfence();
  }
}

__global__ void __launch_bounds__(448, 1) autoint_kernel(Params p)
{
  extern __shared__ float sm[];
  const int tid  = threadIdx.x;
  const int warp = tid >> 5;
  const int lane = tid & 31;
  const int samp  = blockIdx.x * WARPS + warp;
  const int sampc = (samp < BATCH) ? samp : (BATCH - 1);

  ull*   wbufp = (ull*)sm;                // 1024 ull w1 chunk (8KB)
  float* wp   = sm + WBUF + warp * PW;
  float* eB   = wp;
  float* kT   = wp + KT_OFF;
  float* sr   = wp + S_OFF;
  float* mA   = wp + MA_OFF;
  float* mB   = wp + MB_OFF;

  // one-time init: kT row 39 zeros (never overwritten), sr1[39] zero
  for (int i = lane; i < KT_PITCH; i += 32) kT[39*KT_PITCH + i] = 0.f;
  if (lane == 0) sr[40 + 39] = 0.f;

  // ---- embedding gather ----
  {
    const int* xr = p.x + sampc * FF;
    for (int i = lane; i < FF * DD; i += 32) {
      int f = i >> 4, d = i & 15;
      int row = xr[f] + f * VOCAB;
      eB[f * DHD + d] = p.emb[row * DD + d];
    }
  }
  cfence();

  attn_layer<16>(wp, p.wq0, p.wk0, p.wv0, p.wr0, lane);
  attn_layer<32>(wp, p.wq1, p.wk1, p.wv1, p.wr1, lane);
  attn_layer<32>(wp, p.wq2, p.wk2, p.wv2, p.wr2, lane);

  __syncthreads();

  // ---- MLP1: 1248 -> 128. 7 groups of 64 threads; group = 2 samples,
  //      thread covers outputs oo and oo+64. ffma2 over k-pairs. ----
  const int grp = tid >> 6;              // 0..6
  const int oo  = tid & 63;
  const float* hA = sm + WBUF + (2*grp)     * PW;
  const float* hB = sm + WBUF + (2*grp + 1) * PW;
  ull aA0p=0,aA0q=0,aA1p=0,aA1q=0, aB0p=0,aB0q=0,aB1p=0,aB1q=0;
  #pragma unroll 1
  for (int chunk = 0; chunk < 78; chunk++) {
    const int k0 = chunk * 16;
    const float* wsrc = p.w1 + k0 * 128;
    #pragma unroll
    for (int it = 0; it < 3; it++) {
      int idx = tid + 448 * it;
      if (idx < 1024) {
        int pk = idx >> 7, oc = idx & 127;
        wbufp[idx] = pack2(wsrc[(2*pk)*128 + oc], wsrc[(2*pk+1)*128 + oc]);
      }
    }
    __syncthreads();
    #pragma unroll
    for (int pk = 0; pk < 8; pk += 2) {
      ull wA0 = wbufp[pk*128 + oo];
      ull wB0 = wbufp[(pk+1)*128 + oo];
      ull wA1 = wbufp[pk*128 + oo + 64];
      ull wB1 = wbufp[(pk+1)*128 + oo + 64];
      ulonglong2 vA = *(const ulonglong2*)(hA + k0 + 2*pk);
      ulonglong2 vB = *(const ulonglong2*)(hB + k0 + 2*pk);
      aA0p = ffma2(vA.x, wA0, aA0p);  aA0q = ffma2(vA.y, wB0, aA0q);
      aA1p = ffma2(vA.x, wA1, aA1p);  aA1q = ffma2(vA.y, wB1, aA1q);
      aB0p = ffma2(vB.x, wA0, aB0p);  aB0q = ffma2(vB.y, wB0, aB0q);
      aB1p = ffma2(vB.x, wA1, aB1p);  aB1q = ffma2(vB.y, wB1, aB1q);
    }
    __syncthreads();
  }
  {
    float b0 = p.b1[oo], b64 = p.b1[oo + 64];
    float* mAa = sm + WBUF + (2*grp)     * PW + MA_OFF;
    float* mAb = sm + WBUF + (2*grp + 1) * PW + MA_OFF;
    mAa[oo]      = fmaxf(hsum2(fadd2(aA0p, aA0q)) + b0,  0.f);
    mAa[oo + 64] = fmaxf(hsum2(fadd2(aA1p, aA1q)) + b64, 0.f);
    mAb[oo]      = fmaxf(hsum2(fadd2(aB0p, aB0q)) + b0,  0.f);
    mAb[oo + 64] = fmaxf(hsum2(fadd2(aB1p, aB1q)) + b64, 0.f);
  }
  __syncthreads();

  // ---- MLP2: 128 -> 64 (warp-per-sample) ----
  {
    float c0 = p.b2[lane], c1 = p.b2[lane + 32];
    #pragma unroll
    for (int k = 0; k < 128; k += 4) {
      float4 hv = *(const float4*)(mA + k);
      c0 += hv.x*p.w2[(k+0)*64+lane]    + hv.y*p.w2[(k+1)*64+lane]
          + hv.z*p.w2[(k+2)*64+lane]    + hv.w*p.w2[(k+3)*64+lane];
      c1 += hv.x*p.w2[(k+0)*64+lane+32] + hv.y*p.w2[(k+1)*64+lane+32]
          + hv.z*p.w2[(k+2)*64+lane+32] + hv.w*p.w2[(k+3)*64+lane+32];
    }
    mB[lane]      = fmaxf(c0, 0.f);
    mB[lane + 32] = fmaxf(c1, 0.f);
  }
  cfence();

  // ---- MLP3: 64 -> 32 ----
  float d0 = p.b3[lane];
  #pragma unroll
  for (int k = 0; k < 64; k += 4) {
    float4 hv = *(const float4*)(mB + k);
    d0 += hv.x*p.w3[(k+0)*32+lane] + hv.y*p.w3[(k+1)*32+lane]
        + hv.z*p.w3[(k+2)*32+lane] + hv.w*p.w3[(k+3)*32+lane];
  }
  float h3v = fmaxf(d0, 0.f);

  // ---- MLP4: 32 -> 1, sigmoid ----
  float part = h3v * p.w4[lane];
  #pragma unroll
  for (int off = 16; off; off >>= 1) part += __shfl_xor_sync(0xffffffffu, part, off);
  if (lane == 0 && samp < BATCH) {
    float z = part + p.b4[0];
    p.out[samp] = 1.0f / (1.0f + __expf(-z));
  }
}

extern "C" void kernel_launch(void* const* d_in, const int* in_sizes, int n_in,
                              void* d_out, int out_size)
{
  Params p;
  p.x   = (const int*)  d_in[0];
  p.emb = (const float*)d_in[1];
  p.wq0 = (const float*)d_in[2];  p.wk0 = (const float*)d_in[3];
  p.wv0 = (const float*)d_in[4];  p.wr0 = (const float*)d_in[5];
  p.wq1 = (const float*)d_in[6];  p.wk1 = (const float*)d_in[7];
  p.wv1 = (const float*)d_in[8];  p.wr1 = (const float*)d_in[9];
  p.wq2 = (const float*)d_in[10]; p.wk2 = (const float*)d_in[11];
  p.wv2 = (const float*)d_in[12]; p.wr2 = (const float*)d_in[13];
  p.w1  = (const float*)d_in[14]; p.b1  = (const float*)d_in[15];
  p.w2  = (const float*)d_in[16]; p.b2  = (const float*)d_in[17];
  p.w3  = (const float*)d_in[18]; p.b3  = (const float*)d_in[19];
  p.w4  = (const float*)d_in[20]; p.b4  = (const float*)d_in[21];
  p.out = (float*)d_out;

  const int smemBytes = (WBUF + WARPS * PW) * (int)sizeof(float);  // 228,608 B
  cudaFuncSetAttribute(autoint_kernel,
                       cudaFuncAttributeMaxDynamicSharedMemorySize, smemBytes);
  autoint_kernel<<<NCTA, 32 * WARPS, smemBytes>>>(p);
}

// round 12
// speedup vs baseline: 1.0739x; 1.0739x over previous
#include <cuda_runtime.h>
#include <cuda_bf16.h>
#include <math.h>

#define BATCH 16384
#define FF    39
#define DD    16
#define DHD   32
#define VOCAB 10000
#define WARPS 12
#define NCTA  ((BATCH + WARPS - 1) / WARPS)   // 1366

// per-warp shared layout (float indices):
//  e:    [0,1248)        e / R / new-e (pitch 32)
//  kT:   [1248,2608)     40 rows x pitch 34 (row 39 = zeros, survives: qB only
//                        reaches word 2496, pass1 writes rows 0..38)
//  qB:   [1248,2496)     39 x pitch 32, pass2+ (aliases kT rows after klo/khi
//                        are register-loaded)
//  vS:   [2608,3952)     32 x pitch 42, pass-1 V staging (dead after vp load)
//  pbuf: [2608,4168)     39 x pitch 40, pass-3 normalized p rows (over dead vS)
//  mA/mB: [1248,1376)/[1376,1440)  MLP hidden, over dead kT/qB
#define KT_OFF   1248
#define KT_PITCH 34
#define QB_OFF   1248
#define QB_PITCH 32
#define VS_OFF   2608
#define VS_PITCH 42
#define PB_OFF   2608
#define PB_PITCH 40
#define MA_OFF   1248
#define MB_OFF   1376
#define PW       4168
#define WBUF     4096          // CTA-shared w1 chunk: 2048 ull (16KB)

#define LOG2E 1.4426950408889634f

typedef unsigned long long ull;

__device__ __forceinline__ ull ffma2(ull a, ull b, ull c) {
  ull d; asm("fma.rn.f32x2 %0, %1, %2, %3;" : "=l"(d) : "l"(a), "l"(b), "l"(c));
  return d;
}
__device__ __forceinline__ ull fadd2(ull a, ull b) {
  ull d; asm("add.rn.f32x2 %0, %1, %2;" : "=l"(d) : "l"(a), "l"(b));
  return d;
}
__device__ __forceinline__ ull pack2(float lo, float hi) {
  ull v; unsigned int l = __float_as_uint(lo), h = __float_as_uint(hi);
  asm("mov.b64 %0, {%1, %2};" : "=l"(v) : "r"(l), "r"(h));
  return v;
}
__device__ __forceinline__ float hsum2(ull v) {
  unsigned int l, h;
  asm("mov.b64 {%0, %1}, %2;" : "=r"(l), "=r"(h) : "l"(v));
  return __uint_as_float(l) + __uint_as_float(h);
}
__device__ __forceinline__ float frcp(float x) {
  float r; asm("rcp.approx.f32 %0, %1;" : "=f"(r) : "f"(x));
  return r;
}
__device__ __forceinline__ float fex2(float x) {
  float r; asm("ex2.approx.f32 %0, %1;" : "=f"(r) : "f"(x));
  return r;
}
__device__ __forceinline__ void cfence() { asm volatile("" ::: "memory"); }

struct Params {
  const int* x; const float* emb;
  const float* wq0; const float* wk0; const float* wv0; const float* wr0;
  const float* wq1; const float* wk1; const float* wv1; const float* wr1;
  const float* wq2; const float* wk2; const float* wv2; const float* wr2;
  const float* w1; const float* b1; const float* w2; const float* b2;
  const float* w3; const float* b3; const float* w4; const float* b4;
  float* out;
};

template<int DIN>
__device__ __forceinline__ void attn_layer(
    float* wp,
    const float* __restrict__ wq, const float* __restrict__ wk,
    const float* __restrict__ wv, const float* __restrict__ wr, int lane)
{
  float* eB = wp;
  float* kT = wp + KT_OFF;
  float* qB = wp + QB_OFF;
  float* vS = wp + VS_OFF;
  float* pb = wp + PB_OFF;
  constexpr int NP = DIN / 2;

  // ---- Pass 1: K -> kT (transposed), V -> vstage ----
  {
    ull wkp[NP], wvp[NP];
    #pragma unroll
    for (int dp = 0; dp < NP; dp++) {
      wkp[dp] = pack2(wk[(2*dp)*DHD + lane], wk[(2*dp+1)*DHD + lane]);
      wvp[dp] = pack2(wv[(2*dp)*DHD + lane], wv[(2*dp+1)*DHD + lane]);
    }
    #pragma unroll 2
    for (int g = 0; g < FF; g++) {
      const ulonglong2* er = (const ulonglong2*)(eB + g*DHD);
      ull ka = 0ull, kb = 0ull, va = 0ull, vb = 0ull;
      #pragma unroll
      for (int q8 = 0; q8 < NP/2; q8++) {
        ulonglong2 ev = er[q8];
        ka = ffma2(ev.x, wkp[2*q8],   ka);  va = ffma2(ev.x, wvp[2*q8],   va);
        kb = ffma2(ev.y, wkp[2*q8+1], kb);  vb = ffma2(ev.y, wvp[2*q8+1], vb);
      }
      kT[g*KT_PITCH + lane] = hsum2(fadd2(ka, kb));
      vS[lane*VS_PITCH + g] = hsum2(fadd2(va, vb));
    }
  }
  cfence();

  // ---- one-time register loads: K rows (lane, lane+32) and V column ----
  ull klo[16], khi[16], vp[20];
  {
    const int hrow = (lane < 7) ? (lane + 32) : 39;   // row 39 is zeros
    #pragma unroll
    for (int dp = 0; dp < 16; dp++) {
      klo[dp] = *(const ull*)&kT[lane*KT_PITCH + 2*dp];
      khi[dp] = *(const ull*)&kT[hrow*KT_PITCH + 2*dp];
    }
    const float* vr = vS + lane*VS_PITCH;
    #pragma unroll
    for (int gp = 0; gp < 19; gp++)
      vp[gp] = pack2(vr[2*gp], vr[2*gp+1]);
    vp[19] = pack2(vr[38], 0.f);                       // V[39] = 0
  }
  cfence();

  // ---- Pass 2: Q (pre-scaled log2e) -> qB (over dead kT rows), R -> eB ----
  {
    ull wqp[NP], wrp[NP];
    #pragma unroll
    for (int dp = 0; dp < NP; dp++) {
      wqp[dp] = pack2(wq[(2*dp)*DHD + lane] * LOG2E, wq[(2*dp+1)*DHD + lane] * LOG2E);
      wrp[dp] = pack2(wr[(2*dp)*DHD + lane], wr[(2*dp+1)*DHD + lane]);
    }
    #pragma unroll 2
    for (int g = 0; g < FF; g++) {
      const ulonglong2* er = (const ulonglong2*)(eB + g*DHD);
      ull qa = 0ull, qb = 0ull, ra = 0ull, rb = 0ull;
      #pragma unroll
      for (int q8 = 0; q8 < NP/2; q8++) {
        ulonglong2 ev = er[q8];
        qa = ffma2(ev.x, wqp[2*q8],   qa);  ra = ffma2(ev.x, wrp[2*q8],   ra);
        qb = ffma2(ev.y, wqp[2*q8+1], qb);  rb = ffma2(ev.y, wrp[2*q8+1], rb);
      }
      qB[g*QB_PITCH + lane] = hsum2(fadd2(qa, qb));
      eB[g*DHD + lane]      = hsum2(fadd2(ra, rb));   // R over dead e
    }
  }
  cfence();

  const bool has2 = (lane < 7);

  // ---- Pass 3: scores + exp + butterfly-normalize -> pbuf ----
  // Loads only from qB [1248,2496), stores only to pbuf [2608,4168):
  // provably disjoint -> consecutive f-iterations software-pipeline freely.
  #pragma unroll 2
  for (int f = 0; f < FF; f++) {
    const ulonglong2* q2 = (const ulonglong2*)(qB + f*QB_PITCH);
    ull s1a = 0ull, s1b = 0ull, s2a = 0ull, s2b = 0ull;
    #pragma unroll
    for (int q8 = 0; q8 < 8; q8++) {
      ulonglong2 qv = q2[q8];
      s1a = ffma2(qv.x, klo[2*q8],   s1a);  s2a = ffma2(qv.x, khi[2*q8],   s2a);
      s1b = ffma2(qv.y, klo[2*q8+1], s1b);  s2b = ffma2(qv.y, khi[2*q8+1], s2b);
    }
    // scores tiny (inputs ~N(0,0.05)): softmax w/o max-sub; Q pre-scaled, p = 2^s
    float p1 = fex2(hsum2(fadd2(s1a, s1b)));
    float p2 = fex2(hsum2(fadd2(s2a, s2b)));   // lanes 7..31: s2=0 -> p2=1, unused
    float sum = p1 + (has2 ? p2 : 0.f);
    #pragma unroll
    for (int o = 16; o; o >>= 1) sum += __shfl_xor_sync(0xffffffffu, sum, o);
    float inv = frcp(sum);
    pb[f*PB_PITCH + lane] = p1 * inv;           // normalized
    if (has2) pb[f*PB_PITCH + lane + 32] = p2 * inv;
  }
  cfence();

  // ---- Pass 4: AV + residual + relu -> eB ----
  // Loads from pbuf, stores to eB: disjoint -> iterations pipeline freely.
  // pbuf slot 39 holds stale finite data; vp[19].hi = V[39] = 0 nullifies it.
  #pragma unroll 2
  for (int f = 0; f < FF; f++) {
    const ulonglong2* s4 = (const ulonglong2*)(pb + f*PB_PITCH);
    ull aa = 0ull, ab = 0ull;
    #pragma unroll
    for (int g4 = 0; g4 < 10; g4++) {
      ulonglong2 sv = s4[g4];
      aa = ffma2(sv.x, vp[2*g4],   aa);
      ab = ffma2(sv.y, vp[2*g4+1], ab);
    }
    float acc = hsum2(fadd2(aa, ab));          // already normalized
    float r   = eB[f*DHD + lane];
    eB[f*DHD + lane] = fmaxf(acc + r, 0.f);
  }
  cfence();
}

__global__ void __launch_bounds__(384, 1) autoint_kernel(Params p)
{
  extern __shared__ float sm[];
  const int tid  = threadIdx.x;
  const int warp = tid >> 5;
  const int lane = tid & 31;
  const int samp  = blockIdx.x * WARPS + warp;
  const int sampc = (samp < BATCH) ? samp : (BATCH - 1);

  ull*   wbufp = (ull*)sm;                // [16][128] k-paired w1 chunk (16KB)
  float* wp   = sm + WBUF + warp * PW;    // per-warp region
  float* eB   = wp;
  float* kT   = wp + KT_OFF;
  float* mA   = wp + MA_OFF;
  float* mB   = wp + MB_OFF;

  // one-time init: kT row 39 zeros (qB reaches only word 2496; pass1 writes
  // rows 0..38 -> row 39 survives all three layers)
  for (int i = lane; i < KT_PITCH; i += 32) kT[39*KT_PITCH + i] = 0.f;

  // ---- embedding gather ----
  {
    const int* xr = p.x + sampc * FF;
    for (int i = lane; i < FF * DD; i += 32) {
      int f = i >> 4, d = i & 15;
      int row = xr[f] + f * VOCAB;
      eB[f * DHD + d] = p.emb[row * DD + d];
    }
  }
  cfence();

  attn_layer<16>(wp, p.wq0, p.wk0, p.wv0, p.wr0, lane);
  attn_layer<32>(wp, p.wq1, p.wk1, p.wv1, p.wr1, lane);
  attn_layer<32>(wp, p.wq2, p.wk2, p.wv2, p.wr2, lane);

  __syncthreads();

  // ---- MLP1: 1248 -> 128, output-stationary, packed ffma2 over k-pairs ----
  const int o  = tid & 127;
  const int sg = tid >> 7;                // 0..2 -> samples sg*4 .. sg*4+3
  const float* h0 = sm + WBUF + (sg*4 + 0) * PW;
  const float* h1 = sm + WBUF + (sg*4 + 1) * PW;
  const float* h2 = sm + WBUF + (sg*4 + 2) * PW;
  const float* h3 = sm + WBUF + (sg*4 + 3) * PW;
  ull a0p = 0ull, a0q = 0ull, a1p = 0ull, a1q = 0ull;
  ull a2p = 0ull, a2q = 0ull, a3p = 0ull, a3q = 0ull;
  #pragma unroll 1
  for (int chunk = 0; chunk < 39; chunk++) {
    const int k0 = chunk * 32;
    const float* wsrc = p.w1 + k0 * 128;
    #pragma unroll
    for (int it = 0; it < 6; it++) {
      int idx = tid + 384 * it;
      if (idx < 2048) {
        int pk = idx >> 7, oc = idx & 127;
        wbufp[idx] = pack2(wsrc[(2*pk)*128 + oc], wsrc[(2*pk+1)*128 + oc]);
      }
    }
    __syncthreads();
    #pragma unroll
    for (int pk = 0; pk < 16; pk += 2) {
      ull wA = wbufp[pk*128 + o];
      ull wB = wbufp[(pk+1)*128 + o];
      ulonglong2 v0 = *(const ulonglong2*)(h0 + k0 + 2*pk);
      ulonglong2 v1 = *(const ulonglong2*)(h1 + k0 + 2*pk);
      ulonglong2 v2 = *(const ulonglong2*)(h2 + k0 + 2*pk);
      ulonglong2 v3 = *(const ulonglong2*)(h3 + k0 + 2*pk);
      a0p = ffma2(v0.x, wA, a0p);  a0q = ffma2(v0.y, wB, a0q);
      a1p = ffma2(v1.x, wA, a1p);  a1q = ffma2(v1.y, wB, a1q);
      a2p = ffma2(v2.x, wA, a2p);  a2q = ffma2(v2.y, wB, a2q);
      a3p = ffma2(v3.x, wA, a3p);  a3q = ffma2(v3.y, wB, a3q);
    }
    __syncthreads();
  }
  {
    float bb = p.b1[o];
    (sm + WBUF + (sg*4 + 0)*PW + MA_OFF)[o] = fmaxf(hsum2(fadd2(a0p, a0q)) + bb, 0.f);
    (sm + WBUF + (sg*4 + 1)*PW + MA_OFF)[o] = fmaxf(hsum2(fadd2(a1p, a1q)) + bb, 0.f);
    (sm + WBUF + (sg*4 + 2)*PW + MA_OFF)[o] = fmaxf(hsum2(fadd2(a2p, a2q)) + bb, 0.f);
    (sm + WBUF + (sg*4 + 3)*PW + MA_OFF)[o] = fmaxf(hsum2(fadd2(a3p, a3q)) + bb, 0.f);
  }
  __syncthreads();

  // ---- MLP2: 128 -> 64 (warp-per-sample) ----
  {
    float c0 = p.b2[lane], c1 = p.b2[lane + 32];
    #pragma unroll
    for (int k = 0; k < 128; k += 4) {
      float4 hv = *(const float4*)(mA + k);
      c0 += hv.x*p.w2[(k+0)*64+lane]    + hv.y*p.w2[(k+1)*64+lane]
          + hv.z*p.w2[(k+2)*64+lane]    + hv.w*p.w2[(k+3)*64+lane];
      c1 += hv.x*p.w2[(k+0)*64+lane+32] + hv.y*p.w2[(k+1)*64+lane+32]
          + hv.z*p.w2[(k+2)*64+lane+32] + hv.w*p.w2[(k+3)*64+lane+32];
    }
    mB[lane]      = fmaxf(c0, 0.f);
    mB[lane + 32] = fmaxf(c1, 0.f);
  }
  cfence();

  // ---- MLP3: 64 -> 32 ----
  float d0 = p.b3[lane];
  #pragma unroll
  for (int k = 0; k < 64; k += 4) {
    float4 hv = *(const float4*)(mB + k);
    d0 += hv.x*p.w3[(k+0)*32+lane] + hv.y*p.w3[(k+1)*32+lane]
        + hv.z*p.w3[(k+2)*32+lane] + hv.w*p.w3[(k+3)*32+lane];
  }
  float h3v = fmaxf(d0, 0.f);

  // ---- MLP4: 32 -> 1, sigmoid ----
  float part = h3v * p.w4[lane];
  #pragma unroll
  for (int off = 16; off; off >>= 1) part += __shfl_xor_sync(0xffffffffu, part, off);
  if (lane == 0 && samp < BATCH) {
    float z = part + p.b4[0];
    p.out[samp] = 1.0f / (1.0f + __expf(-z));
  }
}

extern "C" void kernel_launch(void* const* d_in, const int* in_sizes, int n_in,
                              void* d_out, int out_size)
{
  Params p;
  p.x   = (const int*)  d_in[0];
  p.emb = (const float*)d_in[1];
  p.wq0 = (const float*)d_in[2];  p.wk0 = (const float*)d_in[3];
  p.wv0 = (const float*)d_in[4];  p.wr0 = (const float*)d_in[5];
  p.wq1 = (const float*)d_in[6];  p.wk1 = (const float*)d_in[7];
  p.wv1 = (const float*)d_in[8];  p.wr1 = (const float*)d_in[9];
  p.wq2 = (const float*)d_in[10]; p.wk2 = (const float*)d_in[11];
  p.wv2 = (const float*)d_in[12]; p.wr2 = (const float*)d_in[13];
  p.w1  = (const float*)d_in[14]; p.b1  = (const float*)d_in[15];
  p.w2  = (const float*)d_in[16]; p.b2  = (const float*)d_in[17];
  p.w3  = (const float*)d_in[18]; p.b3  = (const float*)d_in[19];
  p.w4  = (const float*)d_in[20]; p.b4  = (const float*)d_in[21];
  p.out = (float*)d_out;

  const int smemBytes = (WBUF + WARPS * PW) * (int)sizeof(float);  // 216,448 B
  cudaFuncSetAttribute(autoint_kernel,
                       cudaFuncAttributeMaxDynamicSharedMemorySize, smemBytes);
  autoint_kernel<<<NCTA, 32 * WARPS, smemBytes>>>(p);
}

// round 13
// speedup vs baseline: 1.1009x; 1.0251x over previous
#include <cuda_runtime.h>
#include <cuda_bf16.h>
#include <math.h>

#define BATCH 16384
#define FF    39
#define DD    16
#define DHD   32
#define VOCAB 10000
#define WARPS 12
#define NCTA  ((BATCH + WARPS - 1) / WARPS)   // 1366

// per-warp shared layout (float indices):
//  eB:   [0,1248)       e / R / new-e (pitch 32)
//  tB:   [1248,2496)    T rows (39 x pitch 32)
//  vS:   [2560,3904)    V staging 32 x pitch 42 (dead after vp reg-load)
//  sr0/1:[3904,3984)    p tiles (slot 39 = 0, init once)
//  zrow: [3984,4016)    32 zeros (ehi source for lanes >= 7)
//  mA/mB:[1248,1376)/[1376,1440)  MLP hidden, over dead tB
#define TB_OFF   1248
#define VS_OFF   2560
#define VS_PITCH 42
#define S_OFF    3904
#define ZR_OFF   3984
#define MA_OFF   1248
#define MB_OFF   1376
#define PW       4032
#define WBUF     4096   // CTA-shared: A matrices (first 2640 fl), later w1 chunk

// A matrices (CTA-shared, pitch 33, pre-scaled by LOG2E):
#define A0_OFF 0        // 16 rows x 33 (cols 16..31 zeroed)
#define A1_OFF 528      // 32 x 33
#define A2_OFF 1584     // 32 x 33  (ends 2640)

#define LOG2E 1.4426950408889634f

typedef unsigned long long ull;

__device__ __forceinline__ ull ffma2(ull a, ull b, ull c) {
  ull d; asm("fma.rn.f32x2 %0, %1, %2, %3;" : "=l"(d) : "l"(a), "l"(b), "l"(c));
  return d;
}
__device__ __forceinline__ ull fadd2(ull a, ull b) {
  ull d; asm("add.rn.f32x2 %0, %1, %2;" : "=l"(d) : "l"(a), "l"(b));
  return d;
}
__device__ __forceinline__ ull pack2(float lo, float hi) {
  ull v; unsigned int l = __float_as_uint(lo), h = __float_as_uint(hi);
  asm("mov.b64 %0, {%1, %2};" : "=l"(v) : "r"(l), "r"(h));
  return v;
}
__device__ __forceinline__ float hsum2(ull v) {
  unsigned int l, h;
  asm("mov.b64 {%0, %1}, %2;" : "=r"(l), "=r"(h) : "l"(v));
  return __uint_as_float(l) + __uint_as_float(h);
}
__device__ __forceinline__ float frcp(float x) {
  float r; asm("rcp.approx.f32 %0, %1;" : "=f"(r) : "f"(x));
  return r;
}
__device__ __forceinline__ float fex2(float x) {
  float r; asm("ex2.approx.f32 %0, %1;" : "=f"(r) : "f"(x));
  return r;
}
__device__ __forceinline__ void cfence() { asm volatile("" ::: "memory"); }

struct Params {
  const int* x; const float* emb;
  const float* wq0; const float* wk0; const float* wv0; const float* wr0;
  const float* wq1; const float* wk1; const float* wv1; const float* wr1;
  const float* wq2; const float* wk2; const float* wv2; const float* wr2;
  const float* w1; const float* b1; const float* w2; const float* b2;
  const float* w3; const float* b3; const float* w4; const float* b4;
  float* out;
};

// One attention layer using S = e·A·e^T (A = Wq·Wk^T, CTA-shared, LOG2E-scaled).
// K projection is never computed; T = e·A replaces Q.
template<int DIN>
__device__ __forceinline__ void attn_layer(
    float* wp, const float* __restrict__ Asm,
    const float* __restrict__ wv, const float* __restrict__ wr, int lane)
{
  float* eB  = wp;
  float* tB  = wp + TB_OFF;
  float* vS  = wp + VS_OFF;
  float* sr0 = wp + S_OFF;
  float* sr1 = wp + S_OFF + 40;
  const float* zrow = wp + ZR_OFF;
  constexpr int NP = DIN / 2;

  // ---- Pass V: V -> vstage (transposed). Only wv packs live. ----
  {
    ull wvp[NP];
    #pragma unroll
    for (int dp = 0; dp < NP; dp++)
      wvp[dp] = pack2(wv[(2*dp)*DHD + lane], wv[(2*dp+1)*DHD + lane]);
    #pragma unroll 2
    for (int g = 0; g < FF; g++) {
      const ulonglong2* er = (const ulonglong2*)(eB + g*DHD);
      ull va = 0ull, vb = 0ull;
      #pragma unroll
      for (int q8 = 0; q8 < NP/2; q8++) {
        ulonglong2 ev = er[q8];
        va = ffma2(ev.x, wvp[2*q8],   va);
        vb = ffma2(ev.y, wvp[2*q8+1], vb);
      }
      vS[lane*VS_PITCH + g] = hsum2(fadd2(va, vb));
    }
  }
  cfence();

  // ---- register loads: V column, e rows (lane, lane+32) ----
  ull vp[20], elo[NP], ehi[NP];
  {
    const float* vr = vS + lane*VS_PITCH;
    #pragma unroll
    for (int gp = 0; gp < 19; gp++)
      vp[gp] = pack2(vr[2*gp], vr[2*gp+1]);
    vp[19] = pack2(vr[38], 0.f);                    // V[39] = 0
    const float* lorow = eB + lane*DHD;
    const float* hirow = (lane < 7) ? (eB + (lane+32)*DHD) : zrow;
    #pragma unroll
    for (int dp = 0; dp < NP; dp++) {
      elo[dp] = *(const ull*)&lorow[2*dp];
      ehi[dp] = *(const ull*)&hirow[2*dp];
    }
  }
  cfence();

  // ---- Pass T/R: T = e·A -> tB, R = e·wr -> eB (over dead e) ----
  {
    ull ap[NP], wrp[NP];
    #pragma unroll
    for (int dp = 0; dp < NP; dp++) {
      ap[dp]  = pack2(Asm[(2*dp)*33 + lane], Asm[(2*dp+1)*33 + lane]);
      wrp[dp] = pack2(wr[(2*dp)*DHD + lane], wr[(2*dp+1)*DHD + lane]);
    }
    #pragma unroll 2
    for (int g = 0; g < FF; g++) {
      const ulonglong2* er = (const ulonglong2*)(eB + g*DHD);
      ull qa = 0ull, qb = 0ull, ra = 0ull, rb = 0ull;
      #pragma unroll
      for (int q8 = 0; q8 < NP/2; q8++) {
        ulonglong2 ev = er[q8];
        qa = ffma2(ev.x, ap[2*q8],   qa);  ra = ffma2(ev.x, wrp[2*q8],   ra);
        qb = ffma2(ev.y, ap[2*q8+1], qb);  rb = ffma2(ev.y, wrp[2*q8+1], rb);
      }
      tB[g*DHD + lane] = hsum2(fadd2(qa, qb));
      eB[g*DHD + lane] = hsum2(fadd2(ra, rb));   // R over dead e
    }
  }
  cfence();

  const bool has2 = (lane < 7);

  // ---- Phase B: s = T·e^T, deferred-norm softmax, AV (R6 structure) ----
  #pragma unroll 2
  for (int f = 0; f < FF; f++) {
    float* srf = (f & 1) ? sr1 : sr0;
    const ulonglong2* q2 = (const ulonglong2*)(tB + f*DHD);
    ull s1a = 0ull, s1b = 0ull, s2a = 0ull, s2b = 0ull;
    #pragma unroll
    for (int q8 = 0; q8 < NP/2; q8++) {
      ulonglong2 qv = q2[q8];
      s1a = ffma2(qv.x, elo[2*q8],   s1a);  s2a = ffma2(qv.x, ehi[2*q8],   s2a);
      s1b = ffma2(qv.y, elo[2*q8+1], s1b);  s2b = ffma2(qv.y, ehi[2*q8+1], s2b);
    }
    // scores tiny: softmax w/o max-sub; A pre-scaled by log2e so p = 2^s
    float p1 = fex2(hsum2(fadd2(s1a, s1b)));
    float p2 = fex2(hsum2(fadd2(s2a, s2b)));
    srf[lane] = p1;
    if (has2) srf[lane + 32] = p2;
    cfence();

    const ulonglong2* s4 = (const ulonglong2*)srf;
    ull aa = 0ull, ab = 0ull, ta = 0ull, tb = 0ull;
    #pragma unroll
    for (int g4 = 0; g4 < 10; g4++) {
      ulonglong2 sv = s4[g4];
      aa = ffma2(sv.x, vp[2*g4],   aa);  ta = fadd2(ta, sv.x);
      ab = ffma2(sv.y, vp[2*g4+1], ab);  tb = fadd2(tb, sv.y);
    }
    float sum = hsum2(fadd2(ta, tb));          // Σ p over all 39 (srf[39]=0)
    float inv = frcp(sum);
    float acc = hsum2(fadd2(aa, ab));
    float r   = eB[f*DHD + lane];
    eB[f*DHD + lane] = fmaxf(fmaf(acc, inv, r), 0.f);
    cfence();
  }
}

__global__ void __launch_bounds__(384, 1) autoint_kernel(Params p)
{
  extern __shared__ float sm[];
  const int tid  = threadIdx.x;
  const int warp = tid >> 5;
  const int lane = tid & 31;
  const int samp  = blockIdx.x * WARPS + warp;
  const int sampc = (samp < BATCH) ? samp : (BATCH - 1);

  ull*   wbufp = (ull*)sm;                // later: [16][128] w1 chunk
  float* wp   = sm + WBUF + warp * PW;    // per-warp region
  float* eB   = wp;
  float* sr   = wp + S_OFF;
  float* mA   = wp + MA_OFF;
  float* mB   = wp + MB_OFF;

  // ---- compute A_l = LOG2E * Wq_l Wk_l^T into CTA-shared smem ----
  for (int i = tid; i < 2640; i += 384) sm[i] = 0.f;
  __syncthreads();
  for (int idx = tid; idx < 2304; idx += 384) {
    int a, b; const float *wqp_, *wkp_; float* dst;
    if (idx < 1024)      { a = idx >> 5;          b = idx & 31;
                           wqp_ = p.wq1; wkp_ = p.wk1; dst = sm + A1_OFF; }
    else if (idx < 2048) { a = (idx - 1024) >> 5; b = idx & 31;
                           wqp_ = p.wq2; wkp_ = p.wk2; dst = sm + A2_OFF; }
    else                 { int t = idx - 2048; a = t >> 4; b = t & 15;
                           wqp_ = p.wq0; wkp_ = p.wk0; dst = sm + A0_OFF; }
    const float4* qa4 = (const float4*)(wqp_ + a*DHD);
    const float4* kb4 = (const float4*)(wkp_ + b*DHD);
    float s = 0.f;
    #pragma unroll
    for (int i4 = 0; i4 < 8; i4++) {
      float4 qv = qa4[i4], kv = kb4[i4];
      s += qv.x*kv.x + qv.y*kv.y + qv.z*kv.z + qv.w*kv.w;
    }
    dst[a*33 + b] = s * LOG2E;
  }

  // per-warp init: sr slots 39 zero, zrow zeros
  if (lane == 0) { sr[39] = 0.f; sr[40 + 39] = 0.f; }
  wp[ZR_OFF + lane] = 0.f;

  // ---- embedding gather ----
  {
    const int* xr = p.x + sampc * FF;
    for (int i = lane; i < FF * DD; i += 32) {
      int f = i >> 4, d = i & 15;
      int row = xr[f] + f * VOCAB;
      eB[f * DHD + d] = p.emb[row * DD + d];
    }
  }
  __syncthreads();   // A visible to all warps; gather done per-warp anyway

  attn_layer<16>(wp, sm + A0_OFF, p.wv0, p.wr0, lane);
  attn_layer<32>(wp, sm + A1_OFF, p.wv1, p.wr1, lane);
  attn_layer<32>(wp, sm + A2_OFF, p.wv2, p.wr2, lane);

  __syncthreads();

  // ---- MLP1: 1248 -> 128, output-stationary, packed ffma2 over k-pairs ----
  const int o  = tid & 127;
  const int sg = tid >> 7;                // 0..2 -> samples sg*4 .. sg*4+3
  const float* h0 = sm + WBUF + (sg*4 + 0) * PW;
  const float* h1 = sm + WBUF + (sg*4 + 1) * PW;
  const float* h2 = sm + WBUF + (sg*4 + 2) * PW;
  const float* h3 = sm + WBUF + (sg*4 + 3) * PW;
  ull a0p = 0ull, a0q = 0ull, a1p = 0ull, a1q = 0ull;
  ull a2p = 0ull, a2q = 0ull, a3p = 0ull, a3q = 0ull;
  #pragma unroll 1
  for (int chunk = 0; chunk < 39; chunk++) {
    const int k0 = chunk * 32;
    const float* wsrc = p.w1 + k0 * 128;
    #pragma unroll
    for (int it = 0; it < 6; it++) {
      int idx = tid + 384 * it;
      if (idx < 2048) {
        int pk = idx >> 7, oc = idx & 127;
        wbufp[idx] = pack2(wsrc[(2*pk)*128 + oc], wsrc[(2*pk+1)*128 + oc]);
      }
    }
    __syncthreads();
    #pragma unroll
    for (int pk = 0; pk < 16; pk += 2) {
      ull wA = wbufp[pk*128 + o];
      ull wB = wbufp[(pk+1)*128 + o];
      ulonglong2 v0 = *(const ulonglong2*)(h0 + k0 + 2*pk);
      ulonglong2 v1 = *(const ulonglong2*)(h1 + k0 + 2*pk);
      ulonglong2 v2 = *(const ulonglong2*)(h2 + k0 + 2*pk);
      ulonglong2 v3 = *(const ulonglong2*)(h3 + k0 + 2*pk);
      a0p = ffma2(v0.x, wA, a0p);  a0q = ffma2(v0.y, wB, a0q);
      a1p = ffma2(v1.x, wA, a1p);  a1q = ffma2(v1.y, wB, a1q);
      a2p = ffma2(v2.x, wA, a2p);  a2q = ffma2(v2.y, wB, a2q);
      a3p = ffma2(v3.x, wA, a3p);  a3q = ffma2(v3.y, wB, a3q);
    }
    __syncthreads();
  }
  {
    float bb = p.b1[o];
    (sm + WBUF + (sg*4 + 0)*PW + MA_OFF)[o] = fmaxf(hsum2(fadd2(a0p, a0q)) + bb, 0.f);
    (sm + WBUF + (sg*4 + 1)*PW + MA_OFF)[o] = fmaxf(hsum2(fadd2(a1p, a1q)) + bb, 0.f);
    (sm + WBUF + (sg*4 + 2)*PW + MA_OFF)[o] = fmaxf(hsum2(fadd2(a2p, a2q)) + bb, 0.f);
    (sm + WBUF + (sg*4 + 3)*PW + MA_OFF)[o] = fmaxf(hsum2(fadd2(a3p, a3q)) + bb, 0.f);
  }
  __syncthreads();

  // ---- MLP2: 128 -> 64 (warp-per-sample) ----
  {
    float c0 = p.b2[lane], c1 = p.b2[lane + 32];
    #pragma unroll
    for (int k = 0; k < 128; k += 4) {
      float4 hv = *(const float4*)(mA + k);
      c0 += hv.x*p.w2[(k+0)*64+lane]    + hv.y*p.w2[(k+1)*64+lane]
          + hv.z*p.w2[(k+2)*64+lane]    + hv.w*p.w2[(k+3)*64+lane];
      c1 += hv.x*p.w2[(k+0)*64+lane+32] + hv.y*p.w2[(k+1)*64+lane+32]
          + hv.z*p.w2[(k+2)*64+lane+32] + hv.w*p.w2[(k+3)*64+lane+32];
    }
    mB[lane]      = fmaxf(c0, 0.f);
    mB[lane + 32] = fmaxf(c1, 0.f);
  }
  cfence();

  // ---- MLP3: 64 -> 32 ----
  float d0 = p.b3[lane];
  #pragma unroll
  for (int k = 0; k < 64; k += 4) {
    float4 hv = *(const float4*)(mB + k);
    d0 += hv.x*p.w3[(k+0)*32+lane] + hv.y*p.w3[(k+1)*32+lane]
        + hv.z*p.w3[(k+2)*32+lane] + hv.w*p.w3[(k+3)*32+lane];
  }
  float h3v = fmaxf(d0, 0.f);

  // ---- MLP4: 32 -> 1, sigmoid ----
  float part = h3v * p.w4[lane];
  #pragma unroll
  for (int off = 16; off; off >>= 1) part += __shfl_xor_sync(0xffffffffu, part, off);
  if (lane == 0 && samp < BATCH) {
    float z = part + p.b4[0];
    p.out[samp] = 1.0f / (1.0f + __expf(-z));
  }
}

extern "C" void kernel_launch(void* const* d_in, const int* in_sizes, int n_in,
                              void* d_out, int out_size)
{
  Params p;
  p.x   = (const int*)  d_in[0];
  p.emb = (const float*)d_in[1];
  p.wq0 = (const float*)d_in[2];  p.wk0 = (const float*)d_in[3];
  p.wv0 = (const float*)d_in[4];  p.wr0 = (const float*)d_in[5];
  p.wq1 = (const float*)d_in[6];  p.wk1 = (const float*)d_in[7];
  p.wv1 = (const float*)d_in[8];  p.wr1 = (const float*)d_in[9];
  p.wq2 = (const float*)d_in[10]; p.wk2 = (const float*)d_in[11];
  p.wv2 = (const float*)d_in[12]; p.wr2 = (const float*)d_in[13];
  p.w1  = (const float*)d_in[14]; p.b1  = (const float*)d_in[15];
  p.w2  = (const float*)d_in[16]; p.b2  = (const float*)d_in[17];
  p.w3  = (const float*)d_in[18]; p.b3  = (const float*)d_in[19];
  p.w4  = (const float*)d_in[20]; p.b4  = (const float*)d_in[21];
  p.out = (float*)d_out;

  const int smemBytes = (WBUF + WARPS * PW) * (int)sizeof(float);  // 209,920 B
  cudaFuncSetAttribute(autoint_kernel,
                       cudaFuncAttributeMaxDynamicSharedMemorySize, smemBytes);
  autoint_kernel<<<NCTA, 32 * WARPS, smemBytes>>>(p);
}

// round 14
// speedup vs baseline: 1.1074x; 1.0059x over previous
#include <cuda_runtime.h>
#include <cuda_bf16.h>
#include <math.h>

#define BATCH 16384
#define FF    39
#define DD    16
#define DHD   32
#define VOCAB 10000
#define WARPS 12
#define NCTA  ((BATCH + WARPS - 1) / WARPS)   // 1366

// per-warp shared layout (float indices):
//  eB:   [0,1248)       e / R / new-e (pitch 32)
//  eP:   [1248,2574)    pitch-34 e copy (Pass V) -> dead after elo/ehi reg load
//  tB:   [1248,2496)    T rows (39 x pitch 32), written AFTER eP dies
//  vS:   [2576,3920)    V staging 32 x pitch 42 (dead after vp reg-load)
//  sr0/1:[3920,4000)    p tiles (slot 39 = 0, init once; nothing overwrites)
//  zrow: [4000,4032)    32 zeros (ehi source for lanes >= 7)
//  mA/mB:[1248,1376)/[1376,1440)  MLP hidden, over dead tB
#define EP_OFF   1248
#define EP_PITCH 34
#define TB_OFF   1248
#define VS_OFF   2576
#define VS_PITCH 42
#define S_OFF    3920
#define ZR_OFF   4000
#define MA_OFF   1248
#define MB_OFF   1376
#define PW       4032
#define WBUF     4096   // CTA-shared: A matrices (first 2640 fl), later w1 chunk

// A matrices (CTA-shared, pitch 33, pre-scaled by LOG2E):
#define A0_OFF 0        // 16 rows x 33 (cols 16..31 zeroed)
#define A1_OFF 528      // 32 x 33
#define A2_OFF 1584     // 32 x 33  (ends 2640)

#define LOG2E 1.4426950408889634f

typedef unsigned long long ull;

__device__ __forceinline__ ull ffma2(ull a, ull b, ull c) {
  ull d; asm("fma.rn.f32x2 %0, %1, %2, %3;" : "=l"(d) : "l"(a), "l"(b), "l"(c));
  return d;
}
__device__ __forceinline__ ull fadd2(ull a, ull b) {
  ull d; asm("add.rn.f32x2 %0, %1, %2;" : "=l"(d) : "l"(a), "l"(b));
  return d;
}
__device__ __forceinline__ ull pack2(float lo, float hi) {
  ull v; unsigned int l = __float_as_uint(lo), h = __float_as_uint(hi);
  asm("mov.b64 %0, {%1, %2};" : "=l"(v) : "r"(l), "r"(h));
  return v;
}
__device__ __forceinline__ float hsum2(ull v) {
  unsigned int l, h;
  asm("mov.b64 {%0, %1}, %2;" : "=r"(l), "=r"(h) : "l"(v));
  return __uint_as_float(l) + __uint_as_float(h);
}
__device__ __forceinline__ float frcp(float x) {
  float r; asm("rcp.approx.f32 %0, %1;" : "=f"(r) : "f"(x));
  return r;
}
__device__ __forceinline__ float fex2(float x) {
  float r; asm("ex2.approx.f32 %0, %1;" : "=f"(r) : "f"(x));
  return r;
}
__device__ __forceinline__ void cfence() { asm volatile("" ::: "memory"); }

struct Params {
  const int* x; const float* emb;
  const float* wq0; const float* wk0; const float* wv0; const float* wr0;
  const float* wq1; const float* wk1; const float* wv1; const float* wr1;
  const float* wq2; const float* wk2; const float* wv2; const float* wr2;
  const float* w1; const float* b1; const float* w2; const float* b2;
  const float* w3; const float* b3; const float* w4; const float* b4;
  float* out;
};

// One attention layer using S = e·A·e^T (A = Wq·Wk^T, CTA-shared, LOG2E-scaled).
// K projection never computed; T = e·A replaces Q.
template<int DIN>
__device__ __forceinline__ void attn_layer(
    float* wp, const float* __restrict__ Asm,
    const float* __restrict__ wv, const float* __restrict__ wr, int lane)
{
  float* eB  = wp;
  float* eP  = wp + EP_OFF;
  float* tB  = wp + TB_OFF;
  float* vS  = wp + VS_OFF;
  float* sr0 = wp + S_OFF;
  float* sr1 = wp + S_OFF + 40;
  const float* zrow = wp + ZR_OFF;
  constexpr int NP = DIN / 2;

  // ---- Pass V: V -> vstage (transposed) + pitch-34 e copy for row loads ----
  {
    ull wvp[NP];
    #pragma unroll
    for (int dp = 0; dp < NP; dp++)
      wvp[dp] = pack2(wv[(2*dp)*DHD + lane], wv[(2*dp+1)*DHD + lane]);
    #pragma unroll 2
    for (int g = 0; g < FF; g++) {
      const ulonglong2* er = (const ulonglong2*)(eB + g*DHD);
      ull va = 0ull, vb = 0ull;
      #pragma unroll
      for (int q8 = 0; q8 < NP/2; q8++) {
        ulonglong2 ev = er[q8];
        va = ffma2(ev.x, wvp[2*q8],   va);
        vb = ffma2(ev.y, wvp[2*q8+1], vb);
      }
      vS[lane*VS_PITCH + g] = hsum2(fadd2(va, vb));
      eP[g*EP_PITCH + lane] = eB[g*DHD + lane];   // conflict-free both sides
    }
  }
  cfence();

  // ---- register loads: V column; e rows (lane, lane+32) from PITCH-34 eP ----
  ull vp[20], elo[NP], ehi[NP];
  {
    const float* vr = vS + lane*VS_PITCH;
    #pragma unroll
    for (int gp = 0; gp < 19; gp++)
      vp[gp] = pack2(vr[2*gp], vr[2*gp+1]);
    vp[19] = pack2(vr[38], 0.f);                    // V[39] = 0
    const float* lorow = eP + lane*EP_PITCH;        // 2-way conflicts only
    const float* hirow = (lane < 7) ? (eP + (lane+32)*EP_PITCH) : zrow;
    #pragma unroll
    for (int dp = 0; dp < NP; dp++) {
      elo[dp] = *(const ull*)&lorow[2*dp];
      ehi[dp] = *(const ull*)&hirow[2*dp];
    }
  }
  cfence();

  // ---- Pass T/R: T = e·A -> tB (over dead eP), R = e·wr -> eB (in place) ----
  {
    ull ap[NP], wrp[NP];
    #pragma unroll
    for (int dp = 0; dp < NP; dp++) {
      ap[dp]  = pack2(Asm[(2*dp)*33 + lane], Asm[(2*dp+1)*33 + lane]);
      wrp[dp] = pack2(wr[(2*dp)*DHD + lane], wr[(2*dp+1)*DHD + lane]);
    }
    #pragma unroll 2
    for (int g = 0; g < FF; g++) {
      const ulonglong2* er = (const ulonglong2*)(eB + g*DHD);
      ull qa = 0ull, qb = 0ull, ra = 0ull, rb = 0ull;
      #pragma unroll
      for (int q8 = 0; q8 < NP/2; q8++) {
        ulonglong2 ev = er[q8];
        qa = ffma2(ev.x, ap[2*q8],   qa);  ra = ffma2(ev.x, wrp[2*q8],   ra);
        qb = ffma2(ev.y, ap[2*q8+1], qb);  rb = ffma2(ev.y, wrp[2*q8+1], rb);
      }
      tB[g*DHD + lane] = hsum2(fadd2(qa, qb));
      eB[g*DHD + lane] = hsum2(fadd2(ra, rb));   // R over dead e
    }
  }
  cfence();

  const bool has2 = (lane < 7);

  // ---- Phase B: s = T·e^T, deferred-norm softmax, AV ----
  #pragma unroll 2
  for (int f = 0; f < FF; f++) {
    float* srf = (f & 1) ? sr1 : sr0;
    const ulonglong2* q2 = (const ulonglong2*)(tB + f*DHD);
    ull s1a = 0ull, s1b = 0ull, s2a = 0ull, s2b = 0ull;
    #pragma unroll
    for (int q8 = 0; q8 < NP/2; q8++) {
      ulonglong2 qv = q2[q8];
      s1a = ffma2(qv.x, elo[2*q8],   s1a);  s2a = ffma2(qv.x, ehi[2*q8],   s2a);
      s1b = ffma2(qv.y, elo[2*q8+1], s1b);  s2b = ffma2(qv.y, ehi[2*q8+1], s2b);
    }
    // scores tiny: softmax w/o max-sub; A pre-scaled by log2e so p = 2^s
    float p1 = fex2(hsum2(fadd2(s1a, s1b)));
    float p2 = fex2(hsum2(fadd2(s2a, s2b)));
    srf[lane] = p1;
    if (has2) srf[lane + 32] = p2;
    cfence();

    const ulonglong2* s4 = (const ulonglong2*)srf;
    ull aa = 0ull, ab = 0ull, ta = 0ull, tb = 0ull;
    #pragma unroll
    for (int g4 = 0; g4 < 10; g4++) {
      ulonglong2 sv = s4[g4];
      aa = ffma2(sv.x, vp[2*g4],   aa);  ta = fadd2(ta, sv.x);
      ab = ffma2(sv.y, vp[2*g4+1], ab);  tb = fadd2(tb, sv.y);
    }
    float sum = hsum2(fadd2(ta, tb));          // Σ p over all 39 (srf[39]=0)
    float inv = frcp(sum);
    float acc = hsum2(fadd2(aa, ab));
    float r   = eB[f*DHD + lane];
    eB[f*DHD + lane] = fmaxf(fmaf(acc, inv, r), 0.f);
    cfence();
  }
}

__global__ void __launch_bounds__(384, 1) autoint_kernel(Params p)
{
  extern __shared__ float sm[];
  const int tid  = threadIdx.x;
  const int warp = tid >> 5;
  const int lane = tid & 31;
  const int samp  = blockIdx.x * WARPS + warp;
  const int sampc = (samp < BATCH) ? samp : (BATCH - 1);

  ull*   wbufp = (ull*)sm;                // later: [16][128] w1 chunk
  float* wp   = sm + WBUF + warp * PW;    // per-warp region
  float* eB   = wp;
  float* sr   = wp + S_OFF;
  float* mA   = wp + MA_OFF;
  float* mB   = wp + MB_OFF;

  // ---- compute A_l = LOG2E * Wq_l Wk_l^T into CTA-shared smem ----
  for (int i = tid; i < 2640; i += 384) sm[i] = 0.f;
  __syncthreads();
  for (int idx = tid; idx < 2304; idx += 384) {
    int a, b; const float *wqp_, *wkp_; float* dst;
    if (idx < 1024)      { a = idx >> 5;          b = idx & 31;
                           wqp_ = p.wq1; wkp_ = p.wk1; dst = sm + A1_OFF; }
    else if (idx < 2048) { a = (idx - 1024) >> 5; b = idx & 31;
                           wqp_ = p.wq2; wkp_ = p.wk2; dst = sm + A2_OFF; }
    else                 { int t = idx - 2048; a = t >> 4; b = t & 15;
                           wqp_ = p.wq0; wkp_ = p.wk0; dst = sm + A0_OFF; }
    const float4* qa4 = (const float4*)(wqp_ + a*DHD);
    const float4* kb4 = (const float4*)(wkp_ + b*DHD);
    float s = 0.f;
    #pragma unroll
    for (int i4 = 0; i4 < 8; i4++) {
      float4 qv = qa4[i4], kv = kb4[i4];
      s += qv.x*kv.x + qv.y*kv.y + qv.z*kv.z + qv.w*kv.w;
    }
    dst[a*33 + b] = s * LOG2E;
  }

  // per-warp init: sr slots 39 zero, zrow zeros (nothing overwrites these)
  if (lane == 0) { sr[39] = 0.f; sr[40 + 39] = 0.f; }
  wp[ZR_OFF + lane] = 0.f;

  // ---- embedding gather ----
  {
    const int* xr = p.x + sampc * FF;
    for (int i = lane; i < FF * DD; i += 32) {
      int f = i >> 4, d = i & 15;
      int row = xr[f] + f * VOCAB;
      eB[f * DHD + d] = p.emb[row * DD + d];
    }
  }
  __syncthreads();   // A visible to all warps

  attn_layer<16>(wp, sm + A0_OFF, p.wv0, p.wr0, lane);
  attn_layer<32>(wp, sm + A1_OFF, p.wv1, p.wr1, lane);
  attn_layer<32>(wp, sm + A2_OFF, p.wv2, p.wr2, lane);

  __syncthreads();

  // ---- MLP1: 1248 -> 128, output-stationary, packed ffma2 over k-pairs ----
  const int o  = tid & 127;
  const int sg = tid >> 7;                // 0..2 -> samples sg*4 .. sg*4+3
  const float* h0 = sm + WBUF + (sg*4 + 0) * PW;
  const float* h1 = sm + WBUF + (sg*4 + 1) * PW;
  const float* h2 = sm + WBUF + (sg*4 + 2) * PW;
  const float* h3 = sm + WBUF + (sg*4 + 3) * PW;
  ull a0p = 0ull, a0q = 0ull, a1p = 0ull, a1q = 0ull;
  ull a2p = 0ull, a2q = 0ull, a3p = 0ull, a3q = 0ull;
  #pragma unroll 1
  for (int chunk = 0; chunk < 39; chunk++) {
    const int k0 = chunk * 32;
    const float* wsrc = p.w1 + k0 * 128;
    #pragma unroll
    for (int it = 0; it < 6; it++) {
      int idx = tid + 384 * it;
      if (idx < 2048) {
        int pk = idx >> 7, oc = idx & 127;
        wbufp[idx] = pack2(wsrc[(2*pk)*128 + oc], wsrc[(2*pk+1)*128 + oc]);
      }
    }
    __syncthreads();
    #pragma unroll
    for (int pk = 0; pk < 16; pk += 2) {
      ull wA = wbufp[pk*128 + o];
      ull wB = wbufp[(pk+1)*128 + o];
      ulonglong2 v0 = *(const ulonglong2*)(h0 + k0 + 2*pk);
      ulonglong2 v1 = *(const ulonglong2*)(h1 + k0 + 2*pk);
      ulonglong2 v2 = *(const ulonglong2*)(h2 + k0 + 2*pk);
      ulonglong2 v3 = *(const ulonglong2*)(h3 + k0 + 2*pk);
      a0p = ffma2(v0.x, wA, a0p);  a0q = ffma2(v0.y, wB, a0q);
      a1p = ffma2(v1.x, wA, a1p);  a1q = ffma2(v1.y, wB, a1q);
      a2p = ffma2(v2.x, wA, a2p);  a2q = ffma2(v2.y, wB, a2q);
      a3p = ffma2(v3.x, wA, a3p);  a3q = ffma2(v3.y, wB, a3q);
    }
    __syncthreads();
  }
  {
    float bb = p.b1[o];
    (sm + WBUF + (sg*4 + 0)*PW + MA_OFF)[o] = fmaxf(hsum2(fadd2(a0p, a0q)) + bb, 0.f);
    (sm + WBUF + (sg*4 + 1)*PW + MA_OFF)[o] = fmaxf(hsum2(fadd2(a1p, a1q)) + bb, 0.f);
    (sm + WBUF + (sg*4 + 2)*PW + MA_OFF)[o] = fmaxf(hsum2(fadd2(a2p, a2q)) + bb, 0.f);
    (sm + WBUF + (sg*4 + 3)*PW + MA_OFF)[o] = fmaxf(hsum2(fadd2(a3p, a3q)) + bb, 0.f);
  }
  __syncthreads();

  // ---- MLP2: 128 -> 64 (warp-per-sample) ----
  {
    float c0 = p.b2[lane], c1 = p.b2[lane + 32];
    #pragma unroll
    for (int k = 0; k < 128; k += 4) {
      float4 hv = *(const float4*)(mA + k);
      c0 += hv.x*p.w2[(k+0)*64+lane]    + hv.y*p.w2[(k+1)*64+lane]
          + hv.z*p.w2[(k+2)*64+lane]    + hv.w*p.w2[(k+3)*64+lane];
      c1 += hv.x*p.w2[(k+0)*64+lane+32] + hv.y*p.w2[(k+1)*64+lane+32]
          + hv.z*p.w2[(k+2)*64+lane+32] + hv.w*p.w2[(k+3)*64+lane+32];
    }
    mB[lane]      = fmaxf(c0, 0.f);
    mB[lane + 32] = fmaxf(c1, 0.f);
  }
  cfence();

  // ---- MLP3: 64 -> 32 ----
  float d0 = p.b3[lane];
  #pragma unroll
  for (int k = 0; k < 64; k += 4) {
    float4 hv = *(const float4*)(mB + k);
    d0 += hv.x*p.w3[(k+0)*32+lane] + hv.y*p.w3[(k+1)*32+lane]
        + hv.z*p.w3[(k+2)*32+lane] + hv.w*p.w3[(k+3)*32+lane];
  }
  float h3v = fmaxf(d0, 0.f);

  // ---- MLP4: 32 -> 1, sigmoid ----
  float part = h3v * p.w4[lane];
  #pragma unroll
  for (int off = 16; off; off >>= 1) part += __shfl_xor_sync(0xffffffffu, part, off);
  if (lane == 0 && samp < BATCH) {
    float z = part + p.b4[0];
    p.out[samp] = 1.0f / (1.0f + __expf(-z));
  }
}

extern "C" void kernel_launch(void* const* d_in, const int* in_sizes, int n_in,
                              void* d_out, int out_size)
{
  Params p;
  p.x   = (const int*)  d_in[0];
  p.emb = (const float*)d_in[1];
  p.wq0 = (const float*)d_in[2];  p.wk0 = (const float*)d_in[3];
  p.wv0 = (const float*)d_in[4];  p.wr0 = (const float*)d_in[5];
  p.wq1 = (const float*)d_in[6];  p.wk1 = (const float*)d_in[7];
  p.wv1 = (const float*)d_in[8];  p.wr1 = (const float*)d_in[9];
  p.wq2 = (const float*)d_in[10]; p.wk2 = (const float*)d_in[11];
  p.wv2 = (const float*)d_in[12]; p.wr2 = (const float*)d_in[13];
  p.w1  = (const float*)d_in[14]; p.b1  = (const float*)d_in[15];
  p.w2  = (const float*)d_in[16]; p.b2  = (const float*)d_in[17];
  p.w3  = (const float*)d_in[18]; p.b3  = (const float*)d_in[19];
  p.w4  = (const float*)d_in[20]; p.b4  = (const float*)d_in[21];
  p.out = (float*)d_out;

  const int smemBytes = (WBUF + WARPS * PW) * (int)sizeof(float);  // 209,920 B
  cudaFuncSetAttribute(autoint_kernel,
                       cudaFuncAttributeMaxDynamicSharedMemorySize, smemBytes);
  autoint_kernel<<<NCTA, 32 * WARPS, smemBytes>>>(p);
}

// round 15
// speedup vs baseline: 1.1843x; 1.0695x over previous
#include <cuda_runtime.h>
#include <cuda_bf16.h>
#include <math.h>

#define BATCH 16384
#define FF    39
#define DD    16
#define DHD   32
#define VOCAB 10000
#define WARPS 12
#define NCTA  ((BATCH + WARPS - 1) / WARPS)   // 1366

// ---- K1 per-warp shared layout (float indices) ----
#define EP_OFF   1248
#define EP_PITCH 34
#define TB_OFF   1248
#define VS_OFF   2576
#define VS_PITCH 42
#define S_OFF    3920
#define ZR_OFF   4000
#define PW       4032
#define ABUF     2688        // CTA-shared A matrices (2640 used, 16B-aligned)

#define A0_OFF 0
#define A1_OFF 528
#define A2_OFF 1584

#define LOG2E 1.4426950408889634f

typedef unsigned long long ull;

// 82 MB intermediate: final attention output h = e3 flattened [BATCH][1248]
__device__ float g_h[(size_t)BATCH * 1248];

__device__ __forceinline__ ull ffma2(ull a, ull b, ull c) {
  ull d; asm("fma.rn.f32x2 %0, %1, %2, %3;" : "=l"(d) : "l"(a), "l"(b), "l"(c));
  return d;
}
__device__ __forceinline__ ull fadd2(ull a, ull b) {
  ull d; asm("add.rn.f32x2 %0, %1, %2;" : "=l"(d) : "l"(a), "l"(b));
  return d;
}
__device__ __forceinline__ ull pack2(float lo, float hi) {
  ull v; unsigned int l = __float_as_uint(lo), h = __float_as_uint(hi);
  asm("mov.b64 %0, {%1, %2};" : "=l"(v) : "r"(l), "r"(h));
  return v;
}
__device__ __forceinline__ float hsum2(ull v) {
  unsigned int l, h;
  asm("mov.b64 {%0, %1}, %2;" : "=r"(l), "=r"(h) : "l"(v));
  return __uint_as_float(l) + __uint_as_float(h);
}
__device__ __forceinline__ void unpk2(ull v, float& lo, float& hi) {
  unsigned int l, h;
  asm("mov.b64 {%0, %1}, %2;" : "=r"(l), "=r"(h) : "l"(v));
  lo = __uint_as_float(l); hi = __uint_as_float(h);
}
__device__ __forceinline__ float frcp(float x) {
  float r; asm("rcp.approx.f32 %0, %1;" : "=f"(r) : "f"(x));
  return r;
}
__device__ __forceinline__ float fex2(float x) {
  float r; asm("ex2.approx.f32 %0, %1;" : "=f"(r) : "f"(x));
  return r;
}
__device__ __forceinline__ void cfence() { asm volatile("" ::: "memory"); }

struct Params {
  const int* x; const float* emb;
  const float* wq0; const float* wk0; const float* wv0; const float* wr0;
  const float* wq1; const float* wk1; const float* wv1; const float* wr1;
  const float* wq2; const float* wk2; const float* wv2; const float* wr2;
  const float* w1; const float* b1; const float* w2; const float* b2;
  const float* w3; const float* b3; const float* w4; const float* b4;
  float* out;
};

// ============================ K1: attention ============================

template<int DIN>
__device__ __forceinline__ void attn_layer(
    float* wp, const float* __restrict__ Asm,
    const float* __restrict__ wv, const float* __restrict__ wr, int lane)
{
  float* eB  = wp;
  float* eP  = wp + EP_OFF;
  float* tB  = wp + TB_OFF;
  float* vS  = wp + VS_OFF;
  float* sr0 = wp + S_OFF;
  float* sr1 = wp + S_OFF + 40;
  const float* zrow = wp + ZR_OFF;
  constexpr int NP = DIN / 2;

  // Pass V: V -> vstage (transposed) + pitch-34 e copy
  {
    ull wvp[NP];
    #pragma unroll
    for (int dp = 0; dp < NP; dp++)
      wvp[dp] = pack2(wv[(2*dp)*DHD + lane], wv[(2*dp+1)*DHD + lane]);
    #pragma unroll 2
    for (int g = 0; g < FF; g++) {
      const ulonglong2* er = (const ulonglong2*)(eB + g*DHD);
      ull va = 0ull, vb = 0ull;
      #pragma unroll
      for (int q8 = 0; q8 < NP/2; q8++) {
        ulonglong2 ev = er[q8];
        va = ffma2(ev.x, wvp[2*q8],   va);
        vb = ffma2(ev.y, wvp[2*q8+1], vb);
      }
      vS[lane*VS_PITCH + g] = hsum2(fadd2(va, vb));
      eP[g*EP_PITCH + lane] = eB[g*DHD + lane];
    }
  }
  cfence();

  // register loads: V column; e rows (lane, lane+32) from pitch-34 eP
  ull vp[20], elo[NP], ehi[NP];
  {
    const float* vr = vS + lane*VS_PITCH;
    #pragma unroll
    for (int gp = 0; gp < 19; gp++)
      vp[gp] = pack2(vr[2*gp], vr[2*gp+1]);
    vp[19] = pack2(vr[38], 0.f);
    const float* lorow = eP + lane*EP_PITCH;
    const float* hirow = (lane < 7) ? (eP + (lane+32)*EP_PITCH) : zrow;
    #pragma unroll
    for (int dp = 0; dp < NP; dp++) {
      elo[dp] = *(const ull*)&lorow[2*dp];
      ehi[dp] = *(const ull*)&hirow[2*dp];
    }
  }
  cfence();

  // Pass T/R: T = e·A -> tB (over dead eP), R = e·wr -> eB (in place)
  {
    ull ap[NP], wrp[NP];
    #pragma unroll
    for (int dp = 0; dp < NP; dp++) {
      ap[dp]  = pack2(Asm[(2*dp)*33 + lane], Asm[(2*dp+1)*33 + lane]);
      wrp[dp] = pack2(wr[(2*dp)*DHD + lane], wr[(2*dp+1)*DHD + lane]);
    }
    #pragma unroll 2
    for (int g = 0; g < FF; g++) {
      const ulonglong2* er = (const ulonglong2*)(eB + g*DHD);
      ull qa = 0ull, qb = 0ull, ra = 0ull, rb = 0ull;
      #pragma unroll
      for (int q8 = 0; q8 < NP/2; q8++) {
        ulonglong2 ev = er[q8];
        qa = ffma2(ev.x, ap[2*q8],   qa);  ra = ffma2(ev.x, wrp[2*q8],   ra);
        qb = ffma2(ev.y, ap[2*q8+1], qb);  rb = ffma2(ev.y, wrp[2*q8+1], rb);
      }
      tB[g*DHD + lane] = hsum2(fadd2(qa, qb));
      eB[g*DHD + lane] = hsum2(fadd2(ra, rb));
    }
  }
  cfence();

  const bool has2 = (lane < 7);

  // Phase B: s = T·e^T, deferred-norm softmax, AV
  #pragma unroll 2
  for (int f = 0; f < FF; f++) {
    float* srf = (f & 1) ? sr1 : sr0;
    const ulonglong2* q2 = (const ulonglong2*)(tB + f*DHD);
    ull s1a = 0ull, s1b = 0ull, s2a = 0ull, s2b = 0ull;
    #pragma unroll
    for (int q8 = 0; q8 < NP/2; q8++) {
      ulonglong2 qv = q2[q8];
      s1a = ffma2(qv.x, elo[2*q8],   s1a);  s2a = ffma2(qv.x, ehi[2*q8],   s2a);
      s1b = ffma2(qv.y, elo[2*q8+1], s1b);  s2b = ffma2(qv.y, ehi[2*q8+1], s2b);
    }
    float p1 = fex2(hsum2(fadd2(s1a, s1b)));
    float p2 = fex2(hsum2(fadd2(s2a, s2b)));
    srf[lane] = p1;
    if (has2) srf[lane + 32] = p2;
    cfence();

    const ulonglong2* s4 = (const ulonglong2*)srf;
    ull aa = 0ull, ab = 0ull, ta = 0ull, tb = 0ull;
    #pragma unroll
    for (int g4 = 0; g4 < 10; g4++) {
      ulonglong2 sv = s4[g4];
      aa = ffma2(sv.x, vp[2*g4],   aa);  ta = fadd2(ta, sv.x);
      ab = ffma2(sv.y, vp[2*g4+1], ab);  tb = fadd2(tb, sv.y);
    }
    float sum = hsum2(fadd2(ta, tb));
    float inv = frcp(sum);
    float acc = hsum2(fadd2(aa, ab));
    float r   = eB[f*DHD + lane];
    eB[f*DHD + lane] = fmaxf(fmaf(acc, inv, r), 0.f);
    cfence();
  }
}

__global__ void __launch_bounds__(384, 1) attn_kernel(Params p)
{
  extern __shared__ float sm[];
  const int tid  = threadIdx.x;
  const int warp = tid >> 5;
  const int lane = tid & 31;
  const int samp  = blockIdx.x * WARPS + warp;
  const int sampc = (samp < BATCH) ? samp : (BATCH - 1);

  float* wp = sm + ABUF + warp * PW;
  float* eB = wp;
  float* sr = wp + S_OFF;

  // A_l = LOG2E * Wq_l Wk_l^T (CTA-shared)
  for (int i = tid; i < 2640; i += 384) sm[i] = 0.f;
  __syncthreads();
  for (int idx = tid; idx < 2304; idx += 384) {
    int a, b; const float *wqp_, *wkp_; float* dst;
    if (idx < 1024)      { a = idx >> 5;          b = idx & 31;
                           wqp_ = p.wq1; wkp_ = p.wk1; dst = sm + A1_OFF; }
    else if (idx < 2048) { a = (idx - 1024) >> 5; b = idx & 31;
                           wqp_ = p.wq2; wkp_ = p.wk2; dst = sm + A2_OFF; }
    else                 { int t = idx - 2048; a = t >> 4; b = t & 15;
                           wqp_ = p.wq0; wkp_ = p.wk0; dst = sm + A0_OFF; }
    const float4* qa4 = (const float4*)(wqp_ + a*DHD);
    const float4* kb4 = (const float4*)(wkp_ + b*DHD);
    float s = 0.f;
    #pragma unroll
    for (int i4 = 0; i4 < 8; i4++) {
      float4 qv = qa4[i4], kv = kb4[i4];
      s += qv.x*kv.x + qv.y*kv.y + qv.z*kv.z + qv.w*kv.w;
    }
    dst[a*33 + b] = s * LOG2E;
  }

  if (lane == 0) { sr[39] = 0.f; sr[40 + 39] = 0.f; }
  wp[ZR_OFF + lane] = 0.f;

  // embedding gather
  {
    const int* xr = p.x + sampc * FF;
    for (int i = lane; i < FF * DD; i += 32) {
      int f = i >> 4, d = i & 15;
      int row = xr[f] + f * VOCAB;
      eB[f * DHD + d] = p.emb[row * DD + d];
    }
  }
  __syncthreads();

  attn_layer<16>(wp, sm + A0_OFF, p.wv0, p.wr0, lane);
  attn_layer<32>(wp, sm + A1_OFF, p.wv1, p.wr1, lane);
  attn_layer<32>(wp, sm + A2_OFF, p.wv2, p.wr2, lane);

  // write final e to global scratch (coalesced 128B rows)
  if (samp < BATCH) {
    float* dst = g_h + (size_t)samp * 1248;
    #pragma unroll 4
    for (int f = 0; f < FF; f++)
      dst[f*DHD + lane] = eB[f*DHD + lane];
  }
}

// ==================== K2: MLP1 GEMM + MLP2-4 tail ====================
// CTA: 128 samples x 128 outputs. 256 threads, 8x8 micro-tiles, kb=16 double-buffered.

__global__ void __launch_bounds__(256, 1) mlp_kernel(Params p)
{
  extern __shared__ float s2[];
  float* AsB[2] = { s2,        s2 + 2112 };   // [16][132]
  float* BsB[2] = { s2 + 4224, s2 + 6336 };   // [16][132]
  const int tid = threadIdx.x;
  const int tx = tid & 15, ty = tid >> 4;
  const int m0 = blockIdx.x * 128;

  const int lm = tid >> 1;              // A-stage row 0..127
  const int lk = (tid & 1) * 8;         // A-stage k offset 0/8
  const int bk = tid >> 4;              // B-stage k 0..15
  const int bn = (tid & 15) * 8;        // B-stage n

  ull c[8][4];
  #pragma unroll
  for (int i = 0; i < 8; i++)
    #pragma unroll
    for (int j = 0; j < 4; j++) c[i][j] = 0ull;

  // prologue: stage tile 0
  {
    const float* a = g_h + (size_t)(m0 + lm) * 1248 + lk;
    float4 a0 = *(const float4*)a, a1 = *(const float4*)(a + 4);
    const float* b = p.w1 + bk*128 + bn;
    float4 b0 = *(const float4*)b, b1 = *(const float4*)(b + 4);
    float* Ad = AsB[0]; float* Bd = BsB[0];
    Ad[(lk+0)*132+lm]=a0.x; Ad[(lk+1)*132+lm]=a0.y; Ad[(lk+2)*132+lm]=a0.z; Ad[(lk+3)*132+lm]=a0.w;
    Ad[(lk+4)*132+lm]=a1.x; Ad[(lk+5)*132+lm]=a1.y; Ad[(lk+6)*132+lm]=a1.z; Ad[(lk+7)*132+lm]=a1.w;
    *(float4*)&Bd[bk*132+bn] = b0; *(float4*)&Bd[bk*132+bn+4] = b1;
  }
  __syncthreads();

  #pragma unroll 1
  for (int t = 0; t < 78; t++) {
    float4 a0, a1, b0, b1;
    if (t < 77) {
      const float* a = g_h + (size_t)(m0 + lm) * 1248 + (t+1)*16 + lk;
      a0 = *(const float4*)a; a1 = *(const float4*)(a + 4);
      const float* b = p.w1 + ((t+1)*16 + bk)*128 + bn;
      b0 = *(const float4*)b; b1 = *(const float4*)(b + 4);
    }
    const float* Ac = AsB[t & 1];
    const float* Bc = BsB[t & 1];
    #pragma unroll
    for (int kk = 0; kk < 16; kk++) {
      float4 av0 = *(const float4*)&Ac[kk*132 + ty*8];
      float4 av1 = *(const float4*)&Ac[kk*132 + ty*8 + 4];
      float4 bv0 = *(const float4*)&Bc[kk*132 + tx*8];
      float4 bv1 = *(const float4*)&Bc[kk*132 + tx*8 + 4];
      ull bp0 = pack2(bv0.x, bv0.y), bp1 = pack2(bv0.z, bv0.w);
      ull bp2 = pack2(bv1.x, bv1.y), bp3 = pack2(bv1.z, bv1.w);
      float av[8] = {av0.x, av0.y, av0.z, av0.w, av1.x, av1.y, av1.z, av1.w};
      #pragma unroll
      for (int i = 0; i < 8; i++) {
        ull ad = pack2(av[i], av[i]);
        c[i][0] = ffma2(ad, bp0, c[i][0]);
        c[i][1] = ffma2(ad, bp1, c[i][1]);
        c[i][2] = ffma2(ad, bp2, c[i][2]);
        c[i][3] = ffma2(ad, bp3, c[i][3]);
      }
    }
    if (t < 77) {
      float* Ad = AsB[(t+1) & 1]; float* Bd = BsB[(t+1) & 1];
      Ad[(lk+0)*132+lm]=a0.x; Ad[(lk+1)*132+lm]=a0.y; Ad[(lk+2)*132+lm]=a0.z; Ad[(lk+3)*132+lm]=a0.w;
      Ad[(lk+4)*132+lm]=a1.x; Ad[(lk+5)*132+lm]=a1.y; Ad[(lk+6)*132+lm]=a1.z; Ad[(lk+7)*132+lm]=a1.w;
      *(float4*)&Bd[bk*132+bn] = b0; *(float4*)&Bd[bk*132+bn+4] = b1;
    }
    __syncthreads();
  }

  // epilogue: bias + relu -> Hs [128][132] (reuses GEMM smem)
  float* Hs   = s2;                 // 16896 floats
  float* wscr = s2 + 16896;         // 8 warps x 68 scratch
  {
    float bb[8];
    #pragma unroll
    for (int j = 0; j < 8; j++) bb[j] = p.b1[tx*8 + j];
    #pragma unroll
    for (int i = 0; i < 8; i++) {
      int row = ty*8 + i;
      #pragma unroll
      for (int jp = 0; jp < 4; jp++) {
        float lo, hi; unpk2(c[i][jp], lo, hi);
        Hs[row*132 + tx*8 + 2*jp]     = fmaxf(lo + bb[2*jp],     0.f);
        Hs[row*132 + tx*8 + 2*jp + 1] = fmaxf(hi + bb[2*jp + 1], 0.f);
      }
    }
  }
  __syncthreads();

  // MLP2-4: warp-per-sample over the CTA's 128 samples
  const int warp = tid >> 5, lane = tid & 31;
  float* mB = wscr + warp * 68;
  #pragma unroll 1
  for (int sl = warp; sl < 128; sl += 8) {
    const float* hrow = Hs + sl*132;
    float c0 = p.b2[lane], c1 = p.b2[lane + 32];
    #pragma unroll
    for (int k = 0; k < 128; k += 4) {
      float4 hv = *(const float4*)(hrow + k);
      c0 += hv.x*p.w2[(k+0)*64+lane]    + hv.y*p.w2[(k+1)*64+lane]
          + hv.z*p.w2[(k+2)*64+lane]    + hv.w*p.w2[(k+3)*64+lane];
      c1 += hv.x*p.w2[(k+0)*64+lane+32] + hv.y*p.w2[(k+1)*64+lane+32]
          + hv.z*p.w2[(k+2)*64+lane+32] + hv.w*p.w2[(k+3)*64+lane+32];
    }
    mB[lane]      = fmaxf(c0, 0.f);
    mB[lane + 32] = fmaxf(c1, 0.f);
    __syncwarp();

    float d0 = p.b3[lane];
    #pragma unroll
    for (int k = 0; k < 64; k += 4) {
      float4 hv = *(const float4*)(mB + k);
      d0 += hv.x*p.w3[(k+0)*32+lane] + hv.y*p.w3[(k+1)*32+lane]
          + hv.z*p.w3[(k+2)*32+lane] + hv.w*p.w3[(k+3)*32+lane];
    }
    float h3v = fmaxf(d0, 0.f);

    float part = h3v * p.w4[lane];
    #pragma unroll
    for (int off = 16; off; off >>= 1) part += __shfl_xor_sync(0xffffffffu, part, off);
    if (lane == 0) {
      float z = part + p.b4[0];
      p.out[m0 + sl] = 1.0f / (1.0f + __expf(-z));
    }
    __syncwarp();
  }
}

extern "C" void kernel_launch(void* const* d_in, const int* in_sizes, int n_in,
                              void* d_out, int out_size)
{
  Params p;
  p.x   = (const int*)  d_in[0];
  p.emb = (const float*)d_in[1];
  p.wq0 = (const float*)d_in[2];  p.wk0 = (const float*)d_in[3];
  p.wv0 = (const float*)d_in[4];  p.wr0 = (const float*)d_in[5];
  p.wq1 = (const float*)d_in[6];  p.wk1 = (const float*)d_in[7];
  p.wv1 = (const float*)d_in[8];  p.wr1 = (const float*)d_in[9];
  p.wq2 = (const float*)d_in[10]; p.wk2 = (const float*)d_in[11];
  p.wv2 = (const float*)d_in[12]; p.wr2 = (const float*)d_in[13];
  p.w1  = (const float*)d_in[14]; p.b1  = (const float*)d_in[15];
  p.w2  = (const float*)d_in[16]; p.b2  = (const float*)d_in[17];
  p.w3  = (const float*)d_in[18]; p.b3  = (const float*)d_in[19];
  p.w4  = (const float*)d_in[20]; p.b4  = (const float*)d_in[21];
  p.out = (float*)d_out;

  const int smem1 = (ABUF + WARPS * PW) * (int)sizeof(float);      // 204,288 B
  const int smem2 = (16896 + 8 * 68) * (int)sizeof(float);         //  69,760 B
  cudaFuncSetAttribute(attn_kernel,
                       cudaFuncAttributeMaxDynamicSharedMemorySize, smem1);
  cudaFuncSetAttribute(mlp_kernel,
                       cudaFuncAttributeMaxDynamicSharedMemorySize, smem2);

  attn_kernel<<<NCTA, 32 * WARPS, smem1>>>(p);
  mlp_kernel<<<BATCH / 128, 256, smem2>>>(p);
}

// round 16
// speedup vs baseline: 1.3658x; 1.1533x over previous
#include <cuda_runtime.h>
#include <cuda_bf16.h>
#include <mma.h>
#include <math.h>

using namespace nvcuda;

#define BATCH 16384
#define FF    39
#define DD    16
#define DHD   32
#define VOCAB 10000
#define WARPS 12
#define NCTA  ((BATCH + WARPS - 1) / WARPS)   // 1366

// ---- K1 per-warp shared layout (float indices) ----
#define EP_OFF   1248
#define EP_PITCH 34
#define TB_OFF   1248
#define VS_OFF   2576
#define VS_PITCH 42
#define S_OFF    3920
#define ZR_OFF   4000
#define PW       4032
#define ABUF     2688

#define A0_OFF 0
#define A1_OFF 528
#define A2_OFF 1584

#define LOG2E 1.4426950408889634f

typedef unsigned long long ull;

// 41 MB intermediate: final attention output h in bf16, [BATCH][1248]
__device__ __nv_bfloat16 g_hb[(size_t)BATCH * 1248];

__device__ __forceinline__ ull ffma2(ull a, ull b, ull c) {
  ull d; asm("fma.rn.f32x2 %0, %1, %2, %3;" : "=l"(d) : "l"(a), "l"(b), "l"(c));
  return d;
}
__device__ __forceinline__ ull fadd2(ull a, ull b) {
  ull d; asm("add.rn.f32x2 %0, %1, %2;" : "=l"(d) : "l"(a), "l"(b));
  return d;
}
__device__ __forceinline__ ull pack2(float lo, float hi) {
  ull v; unsigned int l = __float_as_uint(lo), h = __float_as_uint(hi);
  asm("mov.b64 %0, {%1, %2};" : "=l"(v) : "r"(l), "r"(h));
  return v;
}
__device__ __forceinline__ float hsum2(ull v) {
  unsigned int l, h;
  asm("mov.b64 {%0, %1}, %2;" : "=r"(l), "=r"(h) : "l"(v));
  return __uint_as_float(l) + __uint_as_float(h);
}
__device__ __forceinline__ float frcp(float x) {
  float r; asm("rcp.approx.f32 %0, %1;" : "=f"(r) : "f"(x));
  return r;
}
__device__ __forceinline__ float fex2(float x) {
  float r; asm("ex2.approx.f32 %0, %1;" : "=f"(r) : "f"(x));
  return r;
}
__device__ __forceinline__ void cfence() { asm volatile("" ::: "memory"); }

struct Params {
  const int* x; const float* emb;
  const float* wq0; const float* wk0; const float* wv0; const float* wr0;
  const float* wq1; const float* wk1; const float* wv1; const float* wr1;
  const float* wq2; const float* wk2; const float* wv2; const float* wr2;
  const float* w1; const float* b1; const float* w2; const float* b2;
  const float* w3; const float* b3; const float* w4; const float* b4;
  float* out;
};

// ============================ K1: attention ============================

template<int DIN>
__device__ __forceinline__ void attn_layer(
    float* wp, const float* __restrict__ Asm,
    const float* __restrict__ wv, const float* __restrict__ wr, int lane)
{
  float* eB  = wp;
  float* eP  = wp + EP_OFF;
  float* tB  = wp + TB_OFF;
  float* vS  = wp + VS_OFF;
  float* sr0 = wp + S_OFF;
  float* sr1 = wp + S_OFF + 40;
  const float* zrow = wp + ZR_OFF;
  constexpr int NP = DIN / 2;

  // Pass V: V -> vstage (transposed) + pitch-34 e copy
  {
    ull wvp[NP];
    #pragma unroll
    for (int dp = 0; dp < NP; dp++)
      wvp[dp] = pack2(wv[(2*dp)*DHD + lane], wv[(2*dp+1)*DHD + lane]);
    #pragma unroll 2
    for (int g = 0; g < FF; g++) {
      const ulonglong2* er = (const ulonglong2*)(eB + g*DHD);
      ull va = 0ull, vb = 0ull;
      #pragma unroll
      for (int q8 = 0; q8 < NP/2; q8++) {
        ulonglong2 ev = er[q8];
        va = ffma2(ev.x, wvp[2*q8],   va);
        vb = ffma2(ev.y, wvp[2*q8+1], vb);
      }
      vS[lane*VS_PITCH + g] = hsum2(fadd2(va, vb));
      eP[g*EP_PITCH + lane] = eB[g*DHD + lane];
    }
  }
  cfence();

  ull vp[20], elo[NP], ehi[NP];
  {
    const float* vr = vS + lane*VS_PITCH;
    #pragma unroll
    for (int gp = 0; gp < 19; gp++)
      vp[gp] = pack2(vr[2*gp], vr[2*gp+1]);
    vp[19] = pack2(vr[38], 0.f);
    const float* lorow = eP + lane*EP_PITCH;
    const float* hirow = (lane < 7) ? (eP + (lane+32)*EP_PITCH) : zrow;
    #pragma unroll
    for (int dp = 0; dp < NP; dp++) {
      elo[dp] = *(const ull*)&lorow[2*dp];
      ehi[dp] = *(const ull*)&hirow[2*dp];
    }
  }
  cfence();

  // Pass T/R
  {
    ull ap[NP], wrp[NP];
    #pragma unroll
    for (int dp = 0; dp < NP; dp++) {
      ap[dp]  = pack2(Asm[(2*dp)*33 + lane], Asm[(2*dp+1)*33 + lane]);
      wrp[dp] = pack2(wr[(2*dp)*DHD + lane], wr[(2*dp+1)*DHD + lane]);
    }
    #pragma unroll 2
    for (int g = 0; g < FF; g++) {
      const ulonglong2* er = (const ulonglong2*)(eB + g*DHD);
      ull qa = 0ull, qb = 0ull, ra = 0ull, rb = 0ull;
      #pragma unroll
      for (int q8 = 0; q8 < NP/2; q8++) {
        ulonglong2 ev = er[q8];
        qa = ffma2(ev.x, ap[2*q8],   qa);  ra = ffma2(ev.x, wrp[2*q8],   ra);
        qb = ffma2(ev.y, ap[2*q8+1], qb);  rb = ffma2(ev.y, wrp[2*q8+1], rb);
      }
      tB[g*DHD + lane] = hsum2(fadd2(qa, qb));
      eB[g*DHD + lane] = hsum2(fadd2(ra, rb));
    }
  }
  cfence();

  const bool has2 = (lane < 7);

  // Phase B
  #pragma unroll 2
  for (int f = 0; f < FF; f++) {
    float* srf = (f & 1) ? sr1 : sr0;
    const ulonglong2* q2 = (const ulonglong2*)(tB + f*DHD);
    ull s1a = 0ull, s1b = 0ull, s2a = 0ull, s2b = 0ull;
    #pragma unroll
    for (int q8 = 0; q8 < NP/2; q8++) {
      ulonglong2 qv = q2[q8];
      s1a = ffma2(qv.x, elo[2*q8],   s1a);  s2a = ffma2(qv.x, ehi[2*q8],   s2a);
      s1b = ffma2(qv.y, elo[2*q8+1], s1b);  s2b = ffma2(qv.y, ehi[2*q8+1], s2b);
    }
    float p1 = fex2(hsum2(fadd2(s1a, s1b)));
    float p2 = fex2(hsum2(fadd2(s2a, s2b)));
    srf[lane] = p1;
    if (has2) srf[lane + 32] = p2;
    cfence();

    const ulonglong2* s4 = (const ulonglong2*)srf;
    ull aa = 0ull, ab = 0ull, ta = 0ull, tb = 0ull;
    #pragma unroll
    for (int g4 = 0; g4 < 10; g4++) {
      ulonglong2 sv = s4[g4];
      aa = ffma2(sv.x, vp[2*g4],   aa);  ta = fadd2(ta, sv.x);
      ab = ffma2(sv.y, vp[2*g4+1], ab);  tb = fadd2(tb, sv.y);
    }
    float sum = hsum2(fadd2(ta, tb));
    float inv = frcp(sum);
    float acc = hsum2(fadd2(aa, ab));
    float r   = eB[f*DHD + lane];
    eB[f*DHD + lane] = fmaxf(fmaf(acc, inv, r), 0.f);
    cfence();
  }
}

__global__ void __launch_bounds__(384, 1) attn_kernel(Params p)
{
  extern __shared__ float sm[];
  const int tid  = threadIdx.x;
  const int warp = tid >> 5;
  const int lane = tid & 31;
  const int samp  = blockIdx.x * WARPS + warp;
  const int sampc = (samp < BATCH) ? samp : (BATCH - 1);

  float* wp = sm + ABUF + warp * PW;
  float* eB = wp;
  float* sr = wp + S_OFF;

  // A_l = LOG2E * Wq_l Wk_l^T (CTA-shared)
  for (int i = tid; i < 2640; i += 384) sm[i] = 0.f;
  __syncthreads();
  for (int idx = tid; idx < 2304; idx += 384) {
    int a, b; const float *wqp_, *wkp_; float* dst;
    if (idx < 1024)      { a = idx >> 5;          b = idx & 31;
                           wqp_ = p.wq1; wkp_ = p.wk1; dst = sm + A1_OFF; }
    else if (idx < 2048) { a = (idx - 1024) >> 5; b = idx & 31;
                           wqp_ = p.wq2; wkp_ = p.wk2; dst = sm + A2_OFF; }
    else                 { int t = idx - 2048; a = t >> 4; b = t & 15;
                           wqp_ = p.wq0; wkp_ = p.wk0; dst = sm + A0_OFF; }
    const float4* qa4 = (const float4*)(wqp_ + a*DHD);
    const float4* kb4 = (const float4*)(wkp_ + b*DHD);
    float s = 0.f;
    #pragma unroll
    for (int i4 = 0; i4 < 8; i4++) {
      float4 qv = qa4[i4], kv = kb4[i4];
      s += qv.x*kv.x + qv.y*kv.y + qv.z*kv.z + qv.w*kv.w;
    }
    dst[a*33 + b] = s * LOG2E;
  }

  if (lane == 0) { sr[39] = 0.f; sr[40 + 39] = 0.f; }
  wp[ZR_OFF + lane] = 0.f;

  // embedding gather
  {
    const int* xr = p.x + sampc * FF;
    for (int i = lane; i < FF * DD; i += 32) {
      int f = i >> 4, d = i & 15;
      int row = xr[f] + f * VOCAB;
      eB[f * DHD + d] = p.emb[row * DD + d];
    }
  }
  __syncthreads();

  attn_layer<16>(wp, sm + A0_OFF, p.wv0, p.wr0, lane);
  attn_layer<32>(wp, sm + A1_OFF, p.wv1, p.wr1, lane);
  attn_layer<32>(wp, sm + A2_OFF, p.wv2, p.wr2, lane);

  // write final e to global scratch as bf16 (coalesced)
  if (samp < BATCH) {
    __nv_bfloat16* dst = g_hb + (size_t)samp * 1248;
    #pragma unroll 4
    for (int f = 0; f < FF; f++)
      dst[f*DHD + lane] = __float2bfloat16(eB[f*DHD + lane]);
  }
}

// ============ K2: wmma bf16 MLP1 GEMM + fused MLP2-4 tail ============
// CTA tile 64m x 128n, grid 256, 8 warps. Warp = 16m x 64n (4 wmma per k-step).

#define MT 64
#define NT 128
#define A_LD 24     // bf16 pitch for As (64 rows x 16 k)
#define B_LD 136    // bf16 pitch for Bs (16 k x 128 n)
#define HS_LD 132   // fp32 pitch for Hs

__global__ void __launch_bounds__(256) mlp_kernel(Params p)
{
  extern __shared__ char s2c[];
  __nv_bfloat16* As[2] = { (__nv_bfloat16*)s2c,
                           (__nv_bfloat16*)s2c + MT*A_LD };
  __nv_bfloat16* Bs[2] = { (__nv_bfloat16*)s2c + 2*MT*A_LD,
                           (__nv_bfloat16*)s2c + 2*MT*A_LD + 16*B_LD };
  float* Hs   = (float*)s2c;
  float* wscr = (float*)s2c + MT*HS_LD;

  const int tid  = threadIdx.x;
  const int warp = tid >> 5;
  const int lane = tid & 31;
  const int m0   = blockIdx.x * MT;

  const int ar = tid >> 2;          // A stage: row 0..63
  const int ak = (tid & 3) * 4;     // A stage: k offset 0/4/8/12
  const int bk = tid >> 4;          // B stage: k 0..15
  const int bn = (tid & 15) * 8;    // B stage: n offset

  const int wm = (warp & 3) * 16;   // warp m offset
  const int wn = (warp >> 2) * 64;  // warp n offset

  wmma::fragment<wmma::accumulator, 16, 16, 16, float> cf[4];
  #pragma unroll
  for (int j = 0; j < 4; j++) wmma::fill_fragment(cf[j], 0.f);

  // stage one 16-k tile into buffer b
  auto stage = [&](int t, int b) {
    // A: 64 x 16 bf16 from g_hb
    *(ull*)&As[b][ar*A_LD + ak] =
        *(const ull*)&g_hb[(size_t)(m0 + ar)*1248 + t*16 + ak];
    // B: 16 x 128, fp32 -> bf16
    const float* ws = p.w1 + (t*16 + bk)*128 + bn;
    float4 w0 = *(const float4*)ws, w1v = *(const float4*)(ws + 4);
    __nv_bfloat16 tmp[8] = {
      __float2bfloat16(w0.x),  __float2bfloat16(w0.y),
      __float2bfloat16(w0.z),  __float2bfloat16(w0.w),
      __float2bfloat16(w1v.x), __float2bfloat16(w1v.y),
      __float2bfloat16(w1v.z), __float2bfloat16(w1v.w) };
    *(uint4*)&Bs[b][bk*B_LD + bn] = *(const uint4*)tmp;
  };

  stage(0, 0);
  __syncthreads();

  #pragma unroll 1
  for (int t = 0; t < 78; t++) {
    if (t < 77) stage(t + 1, (t + 1) & 1);
    const __nv_bfloat16* Ac = As[t & 1];
    const __nv_bfloat16* Bc = Bs[t & 1];
    wmma::fragment<wmma::matrix_a, 16, 16, 16, __nv_bfloat16, wmma::row_major> af;
    wmma::load_matrix_sync(af, Ac + wm*A_LD, A_LD);
    #pragma unroll
    for (int j = 0; j < 4; j++) {
      wmma::fragment<wmma::matrix_b, 16, 16, 16, __nv_bfloat16, wmma::row_major> bf;
      wmma::load_matrix_sync(bf, Bc + wn + j*16, B_LD);
      wmma::mma_sync(cf[j], af, bf, cf[j]);
    }
    __syncthreads();
  }

  // epilogue: C -> Hs (over dead GEMM buffers), bias+relu applied after store
  #pragma unroll
  for (int j = 0; j < 4; j++)
    wmma::store_matrix_sync(Hs + wm*HS_LD + wn + j*16, cf[j], HS_LD,
                            wmma::mem_row_major);
  __syncthreads();
  // bias + relu in place (256 threads x 32 elems)
  {
    const int hr = tid >> 2;          // row 0..63
    const int hc = (tid & 3) * 32;    // col block
    #pragma unroll
    for (int j = 0; j < 32; j++) {
      float v = Hs[hr*HS_LD + hc + j] + p.b1[hc + j];
      Hs[hr*HS_LD + hc + j] = fmaxf(v, 0.f);
    }
  }
  __syncthreads();

  // MLP2-4: warp-per-sample over the CTA's 64 samples
  float* mB = wscr + warp * 68;
  #pragma unroll 1
  for (int sl = warp; sl < MT; sl += 8) {
    const float* hrow = Hs + sl*HS_LD;
    float c0 = p.b2[lane], c1 = p.b2[lane + 32];
    #pragma unroll
    for (int k = 0; k < 128; k += 4) {
      float4 hv = *(const float4*)(hrow + k);
      c0 += hv.x*p.w2[(k+0)*64+lane]    + hv.y*p.w2[(k+1)*64+lane]
          + hv.z*p.w2[(k+2)*64+lane]    + hv.w*p.w2[(k+3)*64+lane];
      c1 += hv.x*p.w2[(k+0)*64+lane+32] + hv.y*p.w2[(k+1)*64+lane+32]
          + hv.z*p.w2[(k+2)*64+lane+32] + hv.w*p.w2[(k+3)*64+lane+32];
    }
    mB[lane]      = fmaxf(c0, 0.f);
    mB[lane + 32] = fmaxf(c1, 0.f);
    __syncwarp();

    float d0 = p.b3[lane];
    #pragma unroll
    for (int k = 0; k < 64; k += 4) {
      float4 hv = *(const float4*)(mB + k);
      d0 += hv.x*p.w3[(k+0)*32+lane] + hv.y*p.w3[(k+1)*32+lane]
          + hv.z*p.w3[(k+2)*32+lane] + hv.w*p.w3[(k+3)*32+lane];
    }
    float h3v = fmaxf(d0, 0.f);

    float part = h3v * p.w4[lane];
    #pragma unroll
    for (int off = 16; off; off >>= 1) part += __shfl_xor_sync(0xffffffffu, part, off);
    if (lane == 0) {
      float z = part + p.b4[0];
      p.out[m0 + sl] = 1.0f / (1.0f + __expf(-z));
    }
    __syncwarp();
  }
}

extern "C" void kernel_launch(void* const* d_in, const int* in_sizes, int n_in,
                              void* d_out, int out_size)
{
  Params p;
  p.x   = (const int*)  d_in[0];
  p.emb = (const float*)d_in[1];
  p.wq0 = (const float*)d_in[2];  p.wk0 = (const float*)d_in[3];
  p.wv0 = (const float*)d_in[4];  p.wr0 = (const float*)d_in[5];
  p.wq1 = (const float*)d_in[6];  p.wk1 = (const float*)d_in[7];
  p.wv1 = (const float*)d_in[8];  p.wv1 = (const float*)d_in[8];
  p.wv1 = (const float*)d_in[8];  p.wr1 = (const float*)d_in[9];
  p.wq2 = (const float*)d_in[10]; p.wk2 = (const float*)d_in[11];
  p.wv2 = (const float*)d_in[12]; p.wr2 = (const float*)d_in[13];
  p.w1  = (const float*)d_in[14]; p.b1  = (const float*)d_in[15];
  p.w2  = (const float*)d_in[16]; p.b2  = (const float*)d_in[17];
  p.w3  = (const float*)d_in[18]; p.b3  = (const float*)d_in[19];
  p.w4  = (const float*)d_in[20]; p.b4  = (const float*)d_in[21];
  p.out = (float*)d_out;

  const int smem1 = (ABUF + WARPS * PW) * (int)sizeof(float);          // 204,288 B
  const int smem2 = (MT*HS_LD + 8*68) * (int)sizeof(float);            //  35,968 B
  cudaFuncSetAttribute(attn_kernel,
                       cudaFuncAttributeMaxDynamicSharedMemorySize, smem1);
  cudaFuncSetAttribute(mlp_kernel,
                       cudaFuncAttributeMaxDynamicSharedMemorySize, smem2);

  attn_kernel<<<NCTA, 32 * WARPS, smem1>>>(p);
  mlp_kernel<<<BATCH / MT, 256, smem2>>>(p);
}